// round 1
// baseline (speedup 1.0000x reference)
#include <cuda_runtime.h>
#include <cuda_bf16.h>
#include <math.h>

#define N_NODES 100000
#define EDGES   300000
#define IN_DIM  10
#define HID     384
#define OUT_DIM 3
#define BN_EPS  1e-5f

// ---------------- scratch (no allocs allowed) ----------------
__device__ float g_bufA[(size_t)N_NODES * HID]; // h (post-activation)
__device__ float g_bufB[(size_t)N_NODES * HID]; // msg / agg / temp
__device__ float g_bufC[(size_t)N_NODES * HID]; // gemm out
__device__ float g_inv[N_NODES];
__device__ int   g_cnt[N_NODES];

// ---------------- degree ----------------
__global__ void k_count(const int* __restrict__ dst) {
    int i = blockIdx.x * blockDim.x + threadIdx.x;
    if (i < EDGES) atomicAdd(&g_cnt[dst[i]], 1);
}

__global__ void k_inv() {
    int i = blockIdx.x * blockDim.x + threadIdx.x;
    if (i < N_NODES) g_inv[i] = 1.0f / fmaxf((float)g_cnt[i], 1.0f);
}

// ---------------- scatter (mean-agg numerator) ----------------
__global__ void k_scatter10(const float* __restrict__ x,
                            float* __restrict__ msg,
                            const int* __restrict__ src,
                            const int* __restrict__ dst) {
    int idx = blockIdx.x * blockDim.x + threadIdx.x;
    if (idx >= EDGES * IN_DIM) return;
    int e = idx / IN_DIM;
    int c = idx - e * IN_DIM;
    int s = __ldg(&src[e]);
    int d = __ldg(&dst[e]);
    atomicAdd(&msg[(size_t)d * IN_DIM + c], __ldg(&x[(size_t)s * IN_DIM + c]));
}

__global__ void k_scatter384(const float* __restrict__ h,
                             float* __restrict__ msg,
                             const int* __restrict__ src,
                             const int* __restrict__ dst) {
    int idx = blockIdx.x * blockDim.x + threadIdx.x;
    if (idx >= EDGES * (HID / 4)) return;
    int e = idx / (HID / 4);
    int c = (idx - e * (HID / 4)) * 4;
    int s = __ldg(&src[e]);
    int d = __ldg(&dst[e]);
    float4 v = *(const float4*)(h + (size_t)s * HID + c);
    float* p = msg + (size_t)d * HID + c;
    atomicAdd(p + 0, v.x);
    atomicAdd(p + 1, v.y);
    atomicAdd(p + 2, v.z);
    atomicAdd(p + 3, v.w);
}

// ---------------- dual-source tiled GEMM ----------------
// out[r][c] = bias[c] + sum_k A0[r][k]*inv[r]*W0[c][k]  (pass 0, inv optional)
//                     + sum_k A1[r][k]*W1[c][k]          (pass 1, optional)
// mode 1: fused BN + ReLU epilogue (per-column stats).
// Tile: BM=128, BN=64, BK=8, 256 threads, 8x4 register blocking.
__global__ __launch_bounds__(256)
void k_gemm(const float* __restrict__ A0, const float* __restrict__ W0,
            const float* __restrict__ A1, const float* __restrict__ W1,
            const float* __restrict__ bias, const float* __restrict__ invp,
            float* __restrict__ out, int M, int K, int NC, int mode,
            const float* __restrict__ bng, const float* __restrict__ bnb,
            const float* __restrict__ bnm, const float* __restrict__ bnv) {
    __shared__ float As[8][132];
    __shared__ float Bs[8][68];

    int tid = threadIdx.x;
    int ty = tid >> 4;           // 0..15 -> 8 rows each
    int tx = tid & 15;           // 0..15 -> 4 cols each
    int bm = blockIdx.y * 128;
    int bn = blockIdx.x * 64;

    float acc[8][4];
#pragma unroll
    for (int i = 0; i < 8; i++)
#pragma unroll
        for (int j = 0; j < 4; j++) acc[i][j] = 0.0f;

    int idA = tid * 4;
    int am = idA >> 3, ak = idA & 7;
    int idB = tid * 2;
    int bj = idB >> 3, bk = idB & 7;

#pragma unroll 1
    for (int pass = 0; pass < 2; pass++) {
        const float* A = pass ? A1 : A0;
        const float* W = pass ? W1 : W0;
        if (A == nullptr) continue;
        float scale = 1.0f;
        if (pass == 0 && invp != nullptr && bm + am < M) scale = invp[bm + am];

        for (int k0 = 0; k0 < K; k0 += 8) {
            // load A tile (128 x 8), transposed into As[k][m]
            {
                const float* ap = A + (size_t)(bm + am) * K + k0 + ak;
                bool rok = (bm + am) < M;
#pragma unroll
                for (int i = 0; i < 4; i++) {
                    float v = 0.0f;
                    if (rok && (k0 + ak + i) < K) v = ap[i];
                    As[ak + i][am] = v * scale;
                }
            }
            // load W tile (64 cols x 8 k) into Bs[k][j]
            {
#pragma unroll
                for (int i = 0; i < 2; i++) {
                    float v = 0.0f;
                    int col = bn + bj, kk = k0 + bk + i;
                    if (col < NC && kk < K) v = W[(size_t)col * K + kk];
                    Bs[bk + i][bj] = v;
                }
            }
            __syncthreads();
#pragma unroll
            for (int k = 0; k < 8; k++) {
                float a[8], b[4];
#pragma unroll
                for (int i = 0; i < 8; i++) a[i] = As[k][ty * 8 + i];
#pragma unroll
                for (int j = 0; j < 4; j++) b[j] = Bs[k][tx * 4 + j];
#pragma unroll
                for (int i = 0; i < 8; i++)
#pragma unroll
                    for (int j = 0; j < 4; j++) acc[i][j] = fmaf(a[i], b[j], acc[i][j]);
            }
            __syncthreads();
        }
    }

#pragma unroll
    for (int i = 0; i < 8; i++) {
        int r = bm + ty * 8 + i;
        if (r >= M) continue;
#pragma unroll
        for (int j = 0; j < 4; j++) {
            int c = bn + tx * 4 + j;
            if (c >= NC) continue;
            float v = acc[i][j] + bias[c];
            if (mode == 1) {
                v = (v - bnm[c]) * rsqrtf(bnv[c] + BN_EPS) * bng[c] + bnb[c];
                v = fmaxf(v, 0.0f);
            }
            out[(size_t)r * NC + c] = v;
        }
    }
}

// ---------------- fused L2 norm + BN + ELU (warp per row) ----------------
__global__ void k_norm_bn_elu(const float* __restrict__ in, float* __restrict__ outp,
                              const float* __restrict__ g, const float* __restrict__ b,
                              const float* __restrict__ m, const float* __restrict__ v) {
    int w = (blockIdx.x * blockDim.x + threadIdx.x) >> 5;
    int lane = threadIdx.x & 31;
    if (w >= N_NODES) return;
    const float* row = in + (size_t)w * HID;
    float vals[12];
    float ss = 0.0f;
#pragma unroll
    for (int i = 0; i < 12; i++) {
        float x = row[lane + 32 * i];
        vals[i] = x;
        ss += x * x;
    }
#pragma unroll
    for (int o = 16; o > 0; o >>= 1) ss += __shfl_xor_sync(0xffffffff, ss, o);
    float inv = 1.0f / fmaxf(sqrtf(ss), 1e-12f);
    float* orow = outp + (size_t)w * HID;
#pragma unroll
    for (int i = 0; i < 12; i++) {
        int c = lane + 32 * i;
        float x = vals[i] * inv;
        x = (x - m[c]) * rsqrtf(v[c] + BN_EPS) * g[c] + b[c];
        x = x > 0.0f ? x : expm1f(x);
        orow[c] = x;
    }
}

// ---------------- final projection 384 -> 3 (warp per row) ----------------
__global__ void k_final(const float* __restrict__ h, const float* __restrict__ W,
                        const float* __restrict__ bias, float* __restrict__ out) {
    int w = (blockIdx.x * blockDim.x + threadIdx.x) >> 5;
    int lane = threadIdx.x & 31;
    if (w >= N_NODES) return;
    const float* row = h + (size_t)w * HID;
    float vals[12];
#pragma unroll
    for (int i = 0; i < 12; i++) vals[i] = row[lane + 32 * i];
#pragma unroll
    for (int o = 0; o < OUT_DIM; o++) {
        float s = 0.0f;
        const float* wr = W + (size_t)o * HID;
#pragma unroll
        for (int i = 0; i < 12; i++) s += vals[i] * __ldg(&wr[lane + 32 * i]);
#pragma unroll
        for (int off = 16; off > 0; off >>= 1) s += __shfl_xor_sync(0xffffffff, s, off);
        if (lane == 0) out[(size_t)w * OUT_DIM + o] = s + bias[o];
    }
}

// ---------------- driver ----------------
extern "C" void kernel_launch(void* const* d_in, const int* in_sizes, int n_in,
                              void* d_out, int out_size) {
    const float* x    = (const float*)d_in[0];
    const int*   ei   = (const int*)d_in[1];
    const float* W_l0 = (const float*)d_in[2];
    const float* b_l0 = (const float*)d_in[3];
    const float* W_r0 = (const float*)d_in[4];
    const float* W_l  = (const float*)d_in[5];
    const float* b_l  = (const float*)d_in[6];
    const float* W_r  = (const float*)d_in[7];
    const float* bn_g = (const float*)d_in[8];
    const float* bn_b = (const float*)d_in[9];
    const float* bn_m = (const float*)d_in[10];
    const float* bn_v = (const float*)d_in[11];
    const float* Wp0  = (const float*)d_in[12];
    const float* bp0  = (const float*)d_in[13];
    const float* Wp1  = (const float*)d_in[14];
    const float* bp1  = (const float*)d_in[15];
    const float* Wp2  = (const float*)d_in[16];
    const float* bp2  = (const float*)d_in[17];
    const float* pbn_g = (const float*)d_in[18];
    const float* pbn_b = (const float*)d_in[19];
    const float* pbn_m = (const float*)d_in[20];
    const float* pbn_v = (const float*)d_in[21];
    float* out = (float*)d_out;

    const int* src = ei;
    const int* dst = ei + EDGES;

    float *bufA, *bufB, *bufC;
    int* cnt;
    cudaGetSymbolAddress((void**)&bufA, g_bufA);
    cudaGetSymbolAddress((void**)&bufB, g_bufB);
    cudaGetSymbolAddress((void**)&bufC, g_bufC);
    cudaGetSymbolAddress((void**)&cnt,  g_cnt);

    // degree + 1/deg
    cudaMemsetAsync(cnt, 0, N_NODES * sizeof(int), 0);
    k_count<<<(EDGES + 255) / 256, 256>>>(dst);
    k_inv<<<(N_NODES + 255) / 256, 256>>>();

    dim3 gg(HID / 64, (N_NODES + 127) / 128);
    int normBlocks = (N_NODES * 32 + 255) / 256;

    // ---- layer 0 (K = 10) ----
    cudaMemsetAsync(bufB, 0, (size_t)N_NODES * IN_DIM * sizeof(float), 0);
    k_scatter10<<<(EDGES * IN_DIM + 255) / 256, 256>>>(x, bufB, src, dst);
    k_gemm<<<gg, 256>>>(bufB, W_l0, x, W_r0, b_l0, (const float*)nullptr /*inv via symbol*/,
                        bufC, N_NODES, IN_DIM, HID, 0,
                        nullptr, nullptr, nullptr, nullptr);
    // NOTE: invp passed via symbol address below instead
    // (fixup: relaunch with proper inv pointer)
    {
        float* invp;
        cudaGetSymbolAddress((void**)&invp, g_inv);
        k_gemm<<<gg, 256>>>(bufB, W_l0, x, W_r0, b_l0, invp,
                            bufC, N_NODES, IN_DIM, HID, 0,
                            nullptr, nullptr, nullptr, nullptr);
        k_norm_bn_elu<<<normBlocks, 256>>>(bufC, bufA, bn_g, bn_b, bn_m, bn_v);

        // ---- layers 1..4 (K = 384) ----
        for (int t = 1; t < 5; t++) {
            cudaMemsetAsync(bufB, 0, (size_t)N_NODES * HID * sizeof(float), 0);
            k_scatter384<<<(EDGES * (HID / 4) + 255) / 256, 256>>>(bufA, bufB, src, dst);
            const float* Wl = W_l + (size_t)(t - 1) * HID * HID;
            const float* Wr = W_r + (size_t)(t - 1) * HID * HID;
            const float* bl = b_l + (size_t)(t - 1) * HID;
            k_gemm<<<gg, 256>>>(bufB, Wl, bufA, Wr, bl, invp,
                                bufC, N_NODES, HID, HID, 0,
                                nullptr, nullptr, nullptr, nullptr);
            k_norm_bn_elu<<<normBlocks, 256>>>(bufC, bufA,
                                               bn_g + t * HID, bn_b + t * HID,
                                               bn_m + t * HID, bn_v + t * HID);
        }
    }

    // ---- projection MLP ----
    k_gemm<<<gg, 256>>>(bufA, Wp0, nullptr, nullptr, bp0, nullptr,
                        bufC, N_NODES, HID, HID, 1,
                        pbn_g, pbn_b, pbn_m, pbn_v);
    k_gemm<<<gg, 256>>>(bufC, Wp1, nullptr, nullptr, bp1, nullptr,
                        bufB, N_NODES, HID, HID, 1,
                        pbn_g + HID, pbn_b + HID, pbn_m + HID, pbn_v + HID);
    k_final<<<normBlocks, 256>>>(bufB, Wp2, bp2, out);
}

// round 7
// speedup vs baseline: 2.5550x; 2.5550x over previous
#include <cuda_runtime.h>
#include <cuda_bf16.h>
#include <math.h>
#include <stdint.h>

#define N_NODES 100000
#define EDGES   300000
#define IN_DIM  10
#define HID     384
#define OUT_DIM 3
#define BN_EPS  1e-5f

// ---------------- scratch (no allocs allowed) ----------------
__device__ float g_bufA[(size_t)N_NODES * HID];
__device__ float g_bufB[(size_t)N_NODES * HID];
__device__ float g_bufC[(size_t)N_NODES * HID];
__device__ float g_agg10[(size_t)N_NODES * IN_DIM];
__device__ float g_inv[N_NODES];
__device__ int   g_cnt[N_NODES];
__device__ int   g_off[N_NODES + 1];
__device__ int   g_cur[N_NODES];
__device__ int   g_csr[EDGES];
__device__ int   g_bsum[256];

// ================= helpers =================
__device__ __forceinline__ uint32_t smem_u32(const void* p) {
    uint32_t a;
    asm("{ .reg .u64 t; cvta.to.shared.u64 t, %1; cvt.u32.u64 %0, t; }" : "=r"(a) : "l"(p));
    return a;
}

#define LDM4(r, a) \
    asm volatile("ldmatrix.sync.aligned.m8n8.x4.shared.b16 {%0,%1,%2,%3}, [%4];" \
        : "=r"((r)[0]), "=r"((r)[1]), "=r"((r)[2]), "=r"((r)[3]) : "r"(a))

#define MMA16816(c, a, b0, b1) \
    asm volatile("mma.sync.aligned.m16n8k16.row.col.f32.bf16.bf16.f32 " \
        "{%0,%1,%2,%3},{%4,%5,%6,%7},{%8,%9},{%0,%1,%2,%3};" \
        : "+f"((c)[0]), "+f"((c)[1]), "+f"((c)[2]), "+f"((c)[3]) \
        : "r"((a)[0]), "r"((a)[1]), "r"((a)[2]), "r"((a)[3]), "r"(b0), "r"(b1))

// ================= graph preprocessing =================
__global__ void k_count(const int* __restrict__ dst) {
    int i = blockIdx.x * blockDim.x + threadIdx.x;
    if (i < EDGES) atomicAdd(&g_cnt[dst[i]], 1);
}
__global__ void k_inv() {
    int i = blockIdx.x * blockDim.x + threadIdx.x;
    if (i < N_NODES) g_inv[i] = 1.0f / fmaxf((float)g_cnt[i], 1.0f);
}
__global__ void k_scan1() {
    __shared__ int s[512];
    int idx = blockIdx.x * 512 + threadIdx.x;
    int v = (idx < N_NODES) ? g_cnt[idx] : 0;
    s[threadIdx.x] = v;
    __syncthreads();
    for (int o = 1; o < 512; o <<= 1) {
        int t = (threadIdx.x >= o) ? s[threadIdx.x - o] : 0;
        __syncthreads();
        s[threadIdx.x] += t;
        __syncthreads();
    }
    if (idx < N_NODES) g_off[idx] = s[threadIdx.x] - v;  // exclusive
    if (threadIdx.x == 511) g_bsum[blockIdx.x] = s[511];
}
__global__ void k_scan2(int nb) {
    if (threadIdx.x == 0) {
        int run = 0;
        for (int i = 0; i < nb; i++) { int t = g_bsum[i]; g_bsum[i] = run; run += t; }
    }
}
__global__ void k_scan3() {
    int idx = blockIdx.x * 512 + threadIdx.x;
    if (idx < N_NODES) {
        int o = g_off[idx] + g_bsum[blockIdx.x];
        g_off[idx] = o;
        g_cur[idx] = o;
    }
    if (idx == 0) g_off[N_NODES] = EDGES;
}
__global__ void k_fill(const int* __restrict__ src, const int* __restrict__ dst) {
    int e = blockIdx.x * blockDim.x + threadIdx.x;
    if (e < EDGES) {
        int p = atomicAdd(&g_cur[dst[e]], 1);
        g_csr[p] = src[e];
    }
}

// ================= mean aggregation (CSR gather) =================
__global__ void k_gather10(const float* __restrict__ x, float* __restrict__ agg) {
    int n = blockIdx.x * blockDim.x + threadIdx.x;
    if (n >= N_NODES) return;
    float acc[IN_DIM];
#pragma unroll
    for (int c = 0; c < IN_DIM; c++) acc[c] = 0.0f;
    int beg = g_off[n], end = g_off[n + 1];
    for (int e = beg; e < end; e++) {
        const float* r = x + (size_t)g_csr[e] * IN_DIM;
#pragma unroll
        for (int c = 0; c < IN_DIM; c++) acc[c] += __ldg(&r[c]);
    }
    float iv = g_inv[n];
#pragma unroll
    for (int c = 0; c < IN_DIM; c++) agg[(size_t)n * IN_DIM + c] = acc[c] * iv;
}

__global__ void k_gather384(const float* __restrict__ h, float* __restrict__ agg) {
    int n = blockIdx.x * 8 + (threadIdx.x >> 5);
    int lane = threadIdx.x & 31;
    if (n >= N_NODES) return;
    int beg = g_off[n], end = g_off[n + 1];
    float4 a0 = make_float4(0, 0, 0, 0), a1 = a0, a2 = a0;
    for (int e = beg; e < end; e++) {
        const float4* r = (const float4*)(h + (size_t)g_csr[e] * HID) + lane;
        float4 v0 = r[0], v1 = r[32], v2 = r[64];
        a0.x += v0.x; a0.y += v0.y; a0.z += v0.z; a0.w += v0.w;
        a1.x += v1.x; a1.y += v1.y; a1.z += v1.z; a1.w += v1.w;
        a2.x += v2.x; a2.y += v2.y; a2.z += v2.z; a2.w += v2.w;
    }
    float iv = g_inv[n];
    a0.x *= iv; a0.y *= iv; a0.z *= iv; a0.w *= iv;
    a1.x *= iv; a1.y *= iv; a1.z *= iv; a1.w *= iv;
    a2.x *= iv; a2.y *= iv; a2.z *= iv; a2.w *= iv;
    float4* o = (float4*)(agg + (size_t)n * HID) + lane;
    o[0] = a0; o[32] = a1; o[64] = a2;
}

// ================= SIMT GEMM (layer 0 only, K=10) =================
__global__ __launch_bounds__(256)
void k_gemm(const float* __restrict__ A0, const float* __restrict__ W0,
            const float* __restrict__ A1, const float* __restrict__ W1,
            const float* __restrict__ bias,
            float* __restrict__ out, int M, int K, int NC) {
    __shared__ float As[8][132];
    __shared__ float Bs[8][68];
    int tid = threadIdx.x;
    int ty = tid >> 4, tx = tid & 15;
    int bm = blockIdx.y * 128, bn = blockIdx.x * 64;

    float acc[8][4];
#pragma unroll
    for (int i = 0; i < 8; i++)
#pragma unroll
        for (int j = 0; j < 4; j++) acc[i][j] = 0.0f;

    int idA = tid * 4, am = idA >> 3, ak = idA & 7;
    int idB = tid * 2, bj = idB >> 3, bk = idB & 7;

#pragma unroll 1
    for (int pass = 0; pass < 2; pass++) {
        const float* A = pass ? A1 : A0;
        const float* W = pass ? W1 : W0;
        if (A == nullptr) continue;
        for (int k0 = 0; k0 < K; k0 += 8) {
            {
                const float* ap = A + (size_t)(bm + am) * K + k0 + ak;
                bool rok = (bm + am) < M;
#pragma unroll
                for (int i = 0; i < 4; i++) {
                    float v = 0.0f;
                    if (rok && (k0 + ak + i) < K) v = ap[i];
                    As[ak + i][am] = v;
                }
            }
            {
#pragma unroll
                for (int i = 0; i < 2; i++) {
                    float v = 0.0f;
                    int col = bn + bj, kk = k0 + bk + i;
                    if (col < NC && kk < K) v = W[(size_t)col * K + kk];
                    Bs[bk + i][bj] = v;
                }
            }
            __syncthreads();
#pragma unroll
            for (int k = 0; k < 8; k++) {
                float a[8], b[4];
#pragma unroll
                for (int i = 0; i < 8; i++) a[i] = As[k][ty * 8 + i];
#pragma unroll
                for (int j = 0; j < 4; j++) b[j] = Bs[k][tx * 4 + j];
#pragma unroll
                for (int i = 0; i < 8; i++)
#pragma unroll
                    for (int j = 0; j < 4; j++) acc[i][j] = fmaf(a[i], b[j], acc[i][j]);
            }
            __syncthreads();
        }
    }
#pragma unroll
    for (int i = 0; i < 8; i++) {
        int r = bm + ty * 8 + i;
        if (r >= M) continue;
#pragma unroll
        for (int j = 0; j < 4; j++) {
            int c = bn + tx * 4 + j;
            if (c >= NC) continue;
            out[(size_t)r * NC + c] = acc[i][j] + bias[c];
        }
    }
}

// ================= HMMA (mma.sync) GEMM with bf16 hi/lo split =================
// out[128 x 128 tile] = sum_src A_src @ W_src^T (+bias, optional BN+ReLU)
// smem tile: 128 rows x 32 k bf16, row stride 80B (pad for ldmatrix conflicts)
#define MM_STRIDE 80
#define MM_TILE   (128 * MM_STRIDE)   // 10240 B
#define OFF_AH    0
#define OFF_AL    (1 * MM_TILE)
#define OFF_BH    (2 * MM_TILE)
#define OFF_BL    (3 * MM_TILE)
#define STAGE_B   (4 * MM_TILE)       // 40960 B
#define SMEM_MMA  (2 * STAGE_B)       // 81920 B

__global__ __launch_bounds__(256, 1)
void k_mma(const float* __restrict__ A0, const float* __restrict__ W0,
           const float* __restrict__ A1, const float* __restrict__ W1,
           const float* __restrict__ bias, float* __restrict__ out, int mode,
           const float* __restrict__ bng, const float* __restrict__ bnb,
           const float* __restrict__ bnm, const float* __restrict__ bnv) {
    extern __shared__ char sm[];
    const int M = N_NODES;
    int tid = threadIdx.x, lane = tid & 31, wid = tid >> 5;
    int bm = blockIdx.y * 128, bn = blockIdx.x * 128;
    int warp_m = wid & 3, warp_n = wid >> 2;   // 4 x 2 warp grid, warp tile 32 x 64

    float acc[2][8][4];
#pragma unroll
    for (int mb = 0; mb < 2; mb++)
#pragma unroll
        for (int nb = 0; nb < 8; nb++)
#pragma unroll
            for (int q = 0; q < 4; q++) acc[mb][nb][q] = 0.0f;

    int lrow = tid >> 1, half = tid & 1;       // loader: 2 threads/row, 16 floats each
    bool aok = (bm + lrow) < M;
    const int nsrc = (A1 != nullptr) ? 2 : 1;
    const int nch = nsrc * 12;                 // K=384 -> 12 chunks of 32 per source

    float4 ra[4], rb[4];

    auto fetch = [&](int ch) {
        const float* A = (ch < 12) ? A0 : A1;
        const float* W = (ch < 12) ? W0 : W1;
        int k0 = ((ch < 12) ? ch : ch - 12) * 32;
        const float4* ap = (const float4*)(A + (size_t)(bm + lrow) * HID + k0 + half * 16);
        const float4* wp = (const float4*)(W + (size_t)(bn + lrow) * HID + k0 + half * 16);
#pragma unroll
        for (int j = 0; j < 4; j++) {
            ra[j] = aok ? ap[j] : make_float4(0, 0, 0, 0);
            rb[j] = wp[j];
        }
    };

    auto sts = [&](int stage) {
        uint4 pah[2], pal[2], pbh[2], pbl[2];
        unsigned short* ah = (unsigned short*)pah;
        unsigned short* al = (unsigned short*)pal;
        unsigned short* bh = (unsigned short*)pbh;
        unsigned short* bl = (unsigned short*)pbl;
        const float* fa = (const float*)ra;
        const float* fb = (const float*)rb;
#pragma unroll
        for (int i = 0; i < 16; i++) {
            __nv_bfloat16 h = __float2bfloat16(fa[i]);
            ah[i] = __bfloat16_as_ushort(h);
            al[i] = __bfloat16_as_ushort(__float2bfloat16(fa[i] - __bfloat162float(h)));
            __nv_bfloat16 g = __float2bfloat16(fb[i]);
            bh[i] = __bfloat16_as_ushort(g);
            bl[i] = __bfloat16_as_ushort(__float2bfloat16(fb[i] - __bfloat162float(g)));
        }
        char* base = sm + stage * STAGE_B + lrow * MM_STRIDE + half * 32;
        *(uint4*)(base + OFF_AH)      = pah[0];
        *(uint4*)(base + OFF_AH + 16) = pah[1];
        *(uint4*)(base + OFF_AL)      = pal[0];
        *(uint4*)(base + OFF_AL + 16) = pal[1];
        *(uint4*)(base + OFF_BH)      = pbh[0];
        *(uint4*)(base + OFF_BH + 16) = pbh[1];
        *(uint4*)(base + OFF_BL)      = pbl[0];
        *(uint4*)(base + OFF_BL + 16) = pbl[1];
    };

    uint32_t smb = smem_u32(sm);
    int l15 = lane & 15, kh = lane >> 4;
    uint32_t aoff = (uint32_t)(warp_m * 32 + l15) * MM_STRIDE + kh * 16;
    uint32_t boff = (uint32_t)(warp_n * 64 + l15) * MM_STRIDE + kh * 16;

    auto mmastage = [&](int stage) {
        uint32_t sb = smb + stage * STAGE_B;
#pragma unroll
        for (int s = 0; s < 2; s++) {           // two k16 steps per 32-chunk
            uint32_t ko = s * 32;               // 16 bf16 = 32 bytes
            uint32_t ahf[2][4], alf[2][4], bhf[4][4], blf[4][4];
#pragma unroll
            for (int mb = 0; mb < 2; mb++) {
                LDM4(ahf[mb], sb + OFF_AH + aoff + mb * (16 * MM_STRIDE) + ko);
                LDM4(alf[mb], sb + OFF_AL + aoff + mb * (16 * MM_STRIDE) + ko);
            }
#pragma unroll
            for (int pb = 0; pb < 4; pb++) {
                LDM4(bhf[pb], sb + OFF_BH + boff + pb * (16 * MM_STRIDE) + ko);
                LDM4(blf[pb], sb + OFF_BL + boff + pb * (16 * MM_STRIDE) + ko);
            }
#pragma unroll
            for (int mb = 0; mb < 2; mb++)
#pragma unroll
                for (int nb = 0; nb < 8; nb++) {
                    int pb = nb >> 1, sel = nb & 1;
                    MMA16816(acc[mb][nb], ahf[mb], bhf[pb][sel], bhf[pb][sel + 2]);
                    MMA16816(acc[mb][nb], ahf[mb], blf[pb][sel], blf[pb][sel + 2]);
                    MMA16816(acc[mb][nb], alf[mb], bhf[pb][sel], bhf[pb][sel + 2]);
                }
        }
    };

    fetch(0);
    sts(0);
    __syncthreads();
#pragma unroll 1
    for (int ch = 0; ch < nch; ch++) {
        if (ch + 1 < nch) fetch(ch + 1);
        mmastage(ch & 1);
        if (ch + 1 < nch) sts((ch + 1) & 1);
        __syncthreads();
    }

    // epilogue
    int g = lane >> 2, tg = lane & 3;
#pragma unroll
    for (int mb = 0; mb < 2; mb++) {
#pragma unroll
        for (int hr = 0; hr < 2; hr++) {
            int r = bm + warp_m * 32 + mb * 16 + g + hr * 8;
            if (r >= M) continue;
            float* orow = out + (size_t)r * HID;
#pragma unroll
            for (int nb = 0; nb < 8; nb++) {
                int c = bn + warp_n * 64 + nb * 8 + tg * 2;
                float v0 = acc[mb][nb][hr * 2 + 0] + __ldg(&bias[c]);
                float v1 = acc[mb][nb][hr * 2 + 1] + __ldg(&bias[c + 1]);
                if (mode == 1) {
                    v0 = (v0 - __ldg(&bnm[c])) * rsqrtf(__ldg(&bnv[c]) + BN_EPS) * __ldg(&bng[c]) + __ldg(&bnb[c]);
                    v1 = (v1 - __ldg(&bnm[c + 1])) * rsqrtf(__ldg(&bnv[c + 1]) + BN_EPS) * __ldg(&bng[c + 1]) + __ldg(&bnb[c + 1]);
                    v0 = fmaxf(v0, 0.0f);
                    v1 = fmaxf(v1, 0.0f);
                }
                *(float2*)(orow + c) = make_float2(v0, v1);
            }
        }
    }
}

// ================= fused L2 norm + BN + ELU =================
__global__ void k_norm_bn_elu(const float* __restrict__ in, float* __restrict__ outp,
                              const float* __restrict__ g, const float* __restrict__ b,
                              const float* __restrict__ m, const float* __restrict__ v) {
    int w = (blockIdx.x * blockDim.x + threadIdx.x) >> 5;
    int lane = threadIdx.x & 31;
    if (w >= N_NODES) return;
    const float* row = in + (size_t)w * HID;
    float vals[12];
    float ss = 0.0f;
#pragma unroll
    for (int i = 0; i < 12; i++) {
        float x = row[lane + 32 * i];
        vals[i] = x;
        ss += x * x;
    }
#pragma unroll
    for (int o = 16; o > 0; o >>= 1) ss += __shfl_xor_sync(0xffffffff, ss, o);
    float inv = 1.0f / fmaxf(sqrtf(ss), 1e-12f);
    float* orow = outp + (size_t)w * HID;
#pragma unroll
    for (int i = 0; i < 12; i++) {
        int c = lane + 32 * i;
        float x = vals[i] * inv;
        x = (x - m[c]) * rsqrtf(v[c] + BN_EPS) * g[c] + b[c];
        x = x > 0.0f ? x : expm1f(x);
        orow[c] = x;
    }
}

// ================= final projection 384 -> 3 =================
__global__ void k_final(const float* __restrict__ h, const float* __restrict__ W,
                        const float* __restrict__ bias, float* __restrict__ out) {
    int w = (blockIdx.x * blockDim.x + threadIdx.x) >> 5;
    int lane = threadIdx.x & 31;
    if (w >= N_NODES) return;
    const float* row = h + (size_t)w * HID;
    float vals[12];
#pragma unroll
    for (int i = 0; i < 12; i++) vals[i] = row[lane + 32 * i];
#pragma unroll
    for (int o = 0; o < OUT_DIM; o++) {
        float s = 0.0f;
        const float* wr = W + (size_t)o * HID;
#pragma unroll
        for (int i = 0; i < 12; i++) s += vals[i] * __ldg(&wr[lane + 32 * i]);
#pragma unroll
        for (int off = 16; off > 0; off >>= 1) s += __shfl_xor_sync(0xffffffff, s, off);
        if (lane == 0) out[(size_t)w * OUT_DIM + o] = s + bias[o];
    }
}

// ================= driver =================
extern "C" void kernel_launch(void* const* d_in, const int* in_sizes, int n_in,
                              void* d_out, int out_size) {
    const float* x    = (const float*)d_in[0];
    const int*   ei   = (const int*)d_in[1];
    const float* W_l0 = (const float*)d_in[2];
    const float* b_l0 = (const float*)d_in[3];
    const float* W_r0 = (const float*)d_in[4];
    const float* W_l  = (const float*)d_in[5];
    const float* b_l  = (const float*)d_in[6];
    const float* W_r  = (const float*)d_in[7];
    const float* bn_g = (const float*)d_in[8];
    const float* bn_b = (const float*)d_in[9];
    const float* bn_m = (const float*)d_in[10];
    const float* bn_v = (const float*)d_in[11];
    const float* Wp0  = (const float*)d_in[12];
    const float* bp0  = (const float*)d_in[13];
    const float* Wp1  = (const float*)d_in[14];
    const float* bp1  = (const float*)d_in[15];
    const float* Wp2  = (const float*)d_in[16];
    const float* bp2  = (const float*)d_in[17];
    const float* pbn_g = (const float*)d_in[18];
    const float* pbn_b = (const float*)d_in[19];
    const float* pbn_m = (const float*)d_in[20];
    const float* pbn_v = (const float*)d_in[21];
    float* out = (float*)d_out;

    const int* src = ei;
    const int* dst = ei + EDGES;

    float *bufA, *bufB, *bufC, *agg10;
    int* cnt;
    cudaGetSymbolAddress((void**)&bufA, g_bufA);
    cudaGetSymbolAddress((void**)&bufB, g_bufB);
    cudaGetSymbolAddress((void**)&bufC, g_bufC);
    cudaGetSymbolAddress((void**)&agg10, g_agg10);
    cudaGetSymbolAddress((void**)&cnt, g_cnt);

    cudaFuncSetAttribute(k_mma, cudaFuncAttributeMaxDynamicSharedMemorySize, SMEM_MMA);

    const int NB = (N_NODES + 511) / 512;  // 196

    // graph preprocessing: degree, 1/deg, CSR
    cudaMemsetAsync(cnt, 0, N_NODES * sizeof(int), 0);
    k_count<<<(EDGES + 255) / 256, 256>>>(dst);
    k_inv<<<(N_NODES + 255) / 256, 256>>>();
    k_scan1<<<NB, 512>>>();
    k_scan2<<<1, 32>>>(NB);
    k_scan3<<<NB, 512>>>();
    k_fill<<<(EDGES + 255) / 256, 256>>>(src, dst);

    const int normBlocks = (N_NODES * 32 + 255) / 256;
    dim3 ggM(3, (N_NODES + 127) / 128);    // 3 col-blocks x 782 row-blocks
    dim3 gg0(HID / 64, (N_NODES + 127) / 128);

    // ---- layer 0 (K=10, SIMT) ----
    k_gather10<<<(N_NODES + 255) / 256, 256>>>(x, agg10);
    k_gemm<<<gg0, 256>>>(agg10, W_l0, x, W_r0, b_l0, bufC, N_NODES, IN_DIM, HID);
    k_norm_bn_elu<<<normBlocks, 256>>>(bufC, bufA, bn_g, bn_b, bn_m, bn_v);

    // ---- layers 1..4 (HMMA) ----
    for (int t = 1; t < 5; t++) {
        k_gather384<<<(N_NODES + 7) / 8, 256>>>(bufA, bufB);
        const float* Wl = W_l + (size_t)(t - 1) * HID * HID;
        const float* Wr = W_r + (size_t)(t - 1) * HID * HID;
        const float* bl = b_l + (size_t)(t - 1) * HID;
        k_mma<<<ggM, 256, SMEM_MMA>>>(bufB, Wl, bufA, Wr, bl, bufC, 0,
                                      nullptr, nullptr, nullptr, nullptr);
        k_norm_bn_elu<<<normBlocks, 256>>>(bufC, bufA,
                                           bn_g + t * HID, bn_b + t * HID,
                                           bn_m + t * HID, bn_v + t * HID);
    }

    // ---- projection MLP (HMMA with fused BN+ReLU) ----
    k_mma<<<ggM, 256, SMEM_MMA>>>(bufA, Wp0, nullptr, nullptr, bp0, bufC, 1,
                                  pbn_g, pbn_b, pbn_m, pbn_v);
    k_mma<<<ggM, 256, SMEM_MMA>>>(bufC, Wp1, nullptr, nullptr, bp1, bufB, 1,
                                  pbn_g + HID, pbn_b + HID, pbn_m + HID, pbn_v + HID);
    k_final<<<normBlocks, 256>>>(bufB, Wp2, bp2, out);
}

// round 12
// speedup vs baseline: 2.6869x; 1.0516x over previous
#include <cuda_runtime.h>
#include <cuda_bf16.h>
#include <math.h>
#include <stdint.h>

#define N_NODES 100000
#define EDGES   300000
#define IN_DIM  10
#define HID     384
#define OUT_DIM 3
#define BN_EPS  1e-5f

typedef unsigned short u16;

// ---------------- scratch (no allocs allowed) ----------------
__device__ float g_bufA[(size_t)N_NODES * HID];   // h post-norm (f32, for gather)
__device__ float g_bufB[(size_t)N_NODES * HID];   // proj1 out (f32)
__device__ float g_bufC[(size_t)N_NODES * HID];   // GEMM out (f32, pre-norm)
__device__ float g_agg10[(size_t)N_NODES * IN_DIM];
__device__ float g_inv[N_NODES];
__device__ int   g_cnt[N_NODES];
__device__ int   g_off[N_NODES + 1];
__device__ int   g_cur[N_NODES];
__device__ int   g_csr[EDGES];
__device__ int   g_bsum[256];
// bf16 hi/lo pre-split operands
__device__ u16 g_whi[10 * HID * HID];
__device__ u16 g_wlo[10 * HID * HID];
__device__ u16 g_hhi[(size_t)N_NODES * HID];
__device__ u16 g_hlo[(size_t)N_NODES * HID];
__device__ u16 g_agh[(size_t)N_NODES * HID];
__device__ u16 g_agl[(size_t)N_NODES * HID];

// ================= helpers =================
__device__ __forceinline__ uint32_t smem_u32(const void* p) {
    uint32_t a;
    asm("{ .reg .u64 t; cvta.to.shared.u64 t, %1; cvt.u32.u64 %0, t; }" : "=r"(a) : "l"(p));
    return a;
}
__device__ __forceinline__ void split_bf16(float v, u16& h, u16& l) {
    __nv_bfloat16 hb = __float2bfloat16(v);
    h = __bfloat16_as_ushort(hb);
    l = __bfloat16_as_ushort(__float2bfloat16(v - __bfloat162float(hb)));
}

#define LDM4(r, a) \
    asm volatile("ldmatrix.sync.aligned.m8n8.x4.shared.b16 {%0,%1,%2,%3}, [%4];" \
        : "=r"((r)[0]), "=r"((r)[1]), "=r"((r)[2]), "=r"((r)[3]) : "r"(a))

#define MMA16816(c, a, b0, b1) \
    asm volatile("mma.sync.aligned.m16n8k16.row.col.f32.bf16.bf16.f32 " \
        "{%0,%1,%2,%3},{%4,%5,%6,%7},{%8,%9},{%0,%1,%2,%3};" \
        : "+f"((c)[0]), "+f"((c)[1]), "+f"((c)[2]), "+f"((c)[3]) \
        : "r"((a)[0]), "r"((a)[1]), "r"((a)[2]), "r"((a)[3]), "r"(b0), "r"(b1))

// ================= graph preprocessing =================
__global__ void k_count(const int* __restrict__ dst) {
    int i = blockIdx.x * blockDim.x + threadIdx.x;
    if (i < EDGES) atomicAdd(&g_cnt[dst[i]], 1);
}
__global__ void k_inv() {
    int i = blockIdx.x * blockDim.x + threadIdx.x;
    if (i < N_NODES) g_inv[i] = 1.0f / fmaxf((float)g_cnt[i], 1.0f);
}
__global__ void k_scan1() {
    __shared__ int s[512];
    int idx = blockIdx.x * 512 + threadIdx.x;
    int v = (idx < N_NODES) ? g_cnt[idx] : 0;
    s[threadIdx.x] = v;
    __syncthreads();
    for (int o = 1; o < 512; o <<= 1) {
        int t = (threadIdx.x >= o) ? s[threadIdx.x - o] : 0;
        __syncthreads();
        s[threadIdx.x] += t;
        __syncthreads();
    }
    if (idx < N_NODES) g_off[idx] = s[threadIdx.x] - v;
    if (threadIdx.x == 511) g_bsum[blockIdx.x] = s[511];
}
__global__ void k_scan2(int nb) {
    if (threadIdx.x == 0) {
        int run = 0;
        for (int i = 0; i < nb; i++) { int t = g_bsum[i]; g_bsum[i] = run; run += t; }
    }
}
__global__ void k_scan3() {
    int idx = blockIdx.x * 512 + threadIdx.x;
    if (idx < N_NODES) {
        int o = g_off[idx] + g_bsum[blockIdx.x];
        g_off[idx] = o;
        g_cur[idx] = o;
    }
    if (idx == 0) g_off[N_NODES] = EDGES;
}
__global__ void k_fill(const int* __restrict__ src, const int* __restrict__ dst) {
    int e = blockIdx.x * blockDim.x + threadIdx.x;
    if (e < EDGES) {
        int p = atomicAdd(&g_cur[dst[e]], 1);
        g_csr[p] = src[e];
    }
}

// ================= weight pre-split =================
__global__ void k_conv(const float* __restrict__ src, u16* __restrict__ hi,
                       u16* __restrict__ lo, int n) {
    int i = blockIdx.x * blockDim.x + threadIdx.x;
    if (i < n) {
        u16 h, l;
        split_bf16(src[i], h, l);
        hi[i] = h;
        lo[i] = l;
    }
}

// ================= mean aggregation (CSR gather) =================
__global__ void k_gather10(const float* __restrict__ x, float* __restrict__ agg) {
    int n = blockIdx.x * blockDim.x + threadIdx.x;
    if (n >= N_NODES) return;
    float acc[IN_DIM];
#pragma unroll
    for (int c = 0; c < IN_DIM; c++) acc[c] = 0.0f;
    int beg = g_off[n], end = g_off[n + 1];
    for (int e = beg; e < end; e++) {
        const float* r = x + (size_t)g_csr[e] * IN_DIM;
#pragma unroll
        for (int c = 0; c < IN_DIM; c++) acc[c] += __ldg(&r[c]);
    }
    float iv = g_inv[n];
#pragma unroll
    for (int c = 0; c < IN_DIM; c++) agg[(size_t)n * IN_DIM + c] = acc[c] * iv;
}

// gather h (f32) -> agg as bf16 hi/lo pair
__global__ void k_gather384(const float* __restrict__ h,
                            u16* __restrict__ aggh, u16* __restrict__ aggl) {
    int n = blockIdx.x * 8 + (threadIdx.x >> 5);
    int lane = threadIdx.x & 31;
    if (n >= N_NODES) return;
    int beg = g_off[n], end = g_off[n + 1];
    float4 a0 = make_float4(0, 0, 0, 0), a1 = a0, a2 = a0;
    for (int e = beg; e < end; e++) {
        const float4* r = (const float4*)(h + (size_t)g_csr[e] * HID) + lane;
        float4 v0 = r[0], v1 = r[32], v2 = r[64];
        a0.x += v0.x; a0.y += v0.y; a0.z += v0.z; a0.w += v0.w;
        a1.x += v1.x; a1.y += v1.y; a1.z += v1.z; a1.w += v1.w;
        a2.x += v2.x; a2.y += v2.y; a2.z += v2.z; a2.w += v2.w;
    }
    float iv = g_inv[n];
    float g4[3][4] = {{a0.x * iv, a0.y * iv, a0.z * iv, a0.w * iv},
                      {a1.x * iv, a1.y * iv, a1.z * iv, a1.w * iv},
                      {a2.x * iv, a2.y * iv, a2.z * iv, a2.w * iv}};
#pragma unroll
    for (int g = 0; g < 3; g++) {
        ushort4 hv, lv;
        split_bf16(g4[g][0], hv.x, lv.x);
        split_bf16(g4[g][1], hv.y, lv.y);
        split_bf16(g4[g][2], hv.z, lv.z);
        split_bf16(g4[g][3], hv.w, lv.w);
        size_t off = (size_t)n * HID + g * 128 + lane * 4;
        *(ushort4*)(aggh + off) = hv;
        *(ushort4*)(aggl + off) = lv;
    }
}

// ================= SIMT GEMM (layer 0 only, K=10) =================
__global__ __launch_bounds__(256)
void k_gemm(const float* __restrict__ A0, const float* __restrict__ W0,
            const float* __restrict__ A1, const float* __restrict__ W1,
            const float* __restrict__ bias,
            float* __restrict__ out, int M, int K, int NC) {
    __shared__ float As[8][132];
    __shared__ float Bs[8][68];
    int tid = threadIdx.x;
    int ty = tid >> 4, tx = tid & 15;
    int bm = blockIdx.y * 128, bn = blockIdx.x * 64;

    float acc[8][4];
#pragma unroll
    for (int i = 0; i < 8; i++)
#pragma unroll
        for (int j = 0; j < 4; j++) acc[i][j] = 0.0f;

    int idA = tid * 4, am = idA >> 3, ak = idA & 7;
    int idB = tid * 2, bj = idB >> 3, bk = idB & 7;

#pragma unroll 1
    for (int pass = 0; pass < 2; pass++) {
        const float* A = pass ? A1 : A0;
        const float* W = pass ? W1 : W0;
        if (A == nullptr) continue;
        for (int k0 = 0; k0 < K; k0 += 8) {
            {
                const float* ap = A + (size_t)(bm + am) * K + k0 + ak;
                bool rok = (bm + am) < M;
#pragma unroll
                for (int i = 0; i < 4; i++) {
                    float v = 0.0f;
                    if (rok && (k0 + ak + i) < K) v = ap[i];
                    As[ak + i][am] = v;
                }
            }
            {
#pragma unroll
                for (int i = 0; i < 2; i++) {
                    float v = 0.0f;
                    int col = bn + bj, kk = k0 + bk + i;
                    if (col < NC && kk < K) v = W[(size_t)col * K + kk];
                    Bs[bk + i][bj] = v;
                }
            }
            __syncthreads();
#pragma unroll
            for (int k = 0; k < 8; k++) {
                float a[8], b[4];
#pragma unroll
                for (int i = 0; i < 8; i++) a[i] = As[k][ty * 8 + i];
#pragma unroll
                for (int j = 0; j < 4; j++) b[j] = Bs[k][tx * 4 + j];
#pragma unroll
                for (int i = 0; i < 8; i++)
#pragma unroll
                    for (int j = 0; j < 4; j++) acc[i][j] = fmaf(a[i], b[j], acc[i][j]);
            }
            __syncthreads();
        }
    }
#pragma unroll
    for (int i = 0; i < 8; i++) {
        int r = bm + ty * 8 + i;
        if (r >= M) continue;
#pragma unroll
        for (int j = 0; j < 4; j++) {
            int c = bn + tx * 4 + j;
            if (c >= NC) continue;
            out[(size_t)r * NC + c] = acc[i][j] + bias[c];
        }
    }
}

// ================= HMMA GEMM, pre-split bf16 operands =================
// mode 0: out = f32 (bias only); mode 1: BN+ReLU -> bf16 pair; mode 2: BN+ReLU -> f32
#define MM_STRIDE 80
#define MM_TILE   (128 * MM_STRIDE)
#define OFF_AH    0
#define OFF_AL    (1 * MM_TILE)
#define OFF_BH    (2 * MM_TILE)
#define OFF_BL    (3 * MM_TILE)
#define STAGE_B   (4 * MM_TILE)
#define SMEM_MMA  (2 * STAGE_B)

__global__ __launch_bounds__(256, 1)
void k_mma(const u16* __restrict__ A0h, const u16* __restrict__ A0l,
           const u16* __restrict__ W0h, const u16* __restrict__ W0l,
           const u16* __restrict__ A1h, const u16* __restrict__ A1l,
           const u16* __restrict__ W1h, const u16* __restrict__ W1l,
           const float* __restrict__ bias, float* __restrict__ outF,
           u16* __restrict__ outHi, u16* __restrict__ outLo, int mode,
           const float* __restrict__ bng, const float* __restrict__ bnb,
           const float* __restrict__ bnm, const float* __restrict__ bnv) {
    extern __shared__ char sm[];
    const int M = N_NODES;
    int tid = threadIdx.x, lane = tid & 31, wid = tid >> 5;
    int bm = blockIdx.y * 128, bn = blockIdx.x * 128;
    int warp_m = wid & 3, warp_n = wid >> 2;

    float acc[2][8][4];
#pragma unroll
    for (int mb = 0; mb < 2; mb++)
#pragma unroll
        for (int nb = 0; nb < 8; nb++)
#pragma unroll
            for (int q = 0; q < 4; q++) acc[mb][nb][q] = 0.0f;

    int lrow = tid >> 1, half = tid & 1;
    bool aok = (bm + lrow) < M;
    const int nsrc = (A1h != nullptr) ? 2 : 1;
    const int nch = nsrc * 12;

    uint4 ra[4], rb[4];   // [0..1]=hi(16 bf16), [2..3]=lo

    auto fetch = [&](int ch) {
        int s = (ch < 12) ? 0 : 1;
        const u16* Ah = s ? A1h : A0h;
        const u16* Al = s ? A1l : A0l;
        const u16* Bh = s ? W1h : W0h;
        const u16* Bl = s ? W1l : W0l;
        int k0 = (ch - s * 12) * 32;
        size_t ao = (size_t)(bm + lrow) * HID + k0 + half * 16;
        size_t bo = (size_t)(bn + lrow) * HID + k0 + half * 16;
        uint4 z = make_uint4(0, 0, 0, 0);
        ra[0] = aok ? *(const uint4*)(Ah + ao) : z;
        ra[1] = aok ? *(const uint4*)(Ah + ao + 8) : z;
        ra[2] = aok ? *(const uint4*)(Al + ao) : z;
        ra[3] = aok ? *(const uint4*)(Al + ao + 8) : z;
        rb[0] = *(const uint4*)(Bh + bo);
        rb[1] = *(const uint4*)(Bh + bo + 8);
        rb[2] = *(const uint4*)(Bl + bo);
        rb[3] = *(const uint4*)(Bl + bo + 8);
    };

    auto sts = [&](int stage) {
        char* base = sm + stage * STAGE_B + lrow * MM_STRIDE + half * 32;
        *(uint4*)(base + OFF_AH)      = ra[0];
        *(uint4*)(base + OFF_AH + 16) = ra[1];
        *(uint4*)(base + OFF_AL)      = ra[2];
        *(uint4*)(base + OFF_AL + 16) = ra[3];
        *(uint4*)(base + OFF_BH)      = rb[0];
        *(uint4*)(base + OFF_BH + 16) = rb[1];
        *(uint4*)(base + OFF_BL)      = rb[2];
        *(uint4*)(base + OFF_BL + 16) = rb[3];
    };

    uint32_t smb = smem_u32(sm);
    int l15 = lane & 15, kh = lane >> 4;
    uint32_t aoff = (uint32_t)(warp_m * 32 + l15) * MM_STRIDE + kh * 16;
    uint32_t boff = (uint32_t)(warp_n * 64 + l15) * MM_STRIDE + kh * 16;

    auto mmastage = [&](int stage) {
        uint32_t sb = smb + stage * STAGE_B;
#pragma unroll
        for (int s = 0; s < 2; s++) {
            uint32_t ko = s * 32;
            uint32_t ahf[2][4], alf[2][4], bhf[4][4], blf[4][4];
#pragma unroll
            for (int mb = 0; mb < 2; mb++) {
                LDM4(ahf[mb], sb + OFF_AH + aoff + mb * (16 * MM_STRIDE) + ko);
                LDM4(alf[mb], sb + OFF_AL + aoff + mb * (16 * MM_STRIDE) + ko);
            }
#pragma unroll
            for (int pb = 0; pb < 4; pb++) {
                LDM4(bhf[pb], sb + OFF_BH + boff + pb * (16 * MM_STRIDE) + ko);
                LDM4(blf[pb], sb + OFF_BL + boff + pb * (16 * MM_STRIDE) + ko);
            }
#pragma unroll
            for (int mb = 0; mb < 2; mb++)
#pragma unroll
                for (int nb = 0; nb < 8; nb++) {
                    int pb = nb >> 1, sel = nb & 1;
                    MMA16816(acc[mb][nb], ahf[mb], bhf[pb][sel], bhf[pb][sel + 2]);
                    MMA16816(acc[mb][nb], ahf[mb], blf[pb][sel], blf[pb][sel + 2]);
                    MMA16816(acc[mb][nb], alf[mb], bhf[pb][sel], bhf[pb][sel + 2]);
                }
        }
    };

    fetch(0);
    sts(0);
    __syncthreads();
#pragma unroll 1
    for (int ch = 0; ch < nch; ch++) {
        if (ch + 1 < nch) fetch(ch + 1);
        mmastage(ch & 1);
        if (ch + 1 < nch) sts((ch + 1) & 1);
        __syncthreads();
    }

    // epilogue
    int g = lane >> 2, tg = lane & 3;
#pragma unroll
    for (int mb = 0; mb < 2; mb++) {
#pragma unroll
        for (int hr = 0; hr < 2; hr++) {
            int r = bm + warp_m * 32 + mb * 16 + g + hr * 8;
            if (r >= M) continue;
#pragma unroll
            for (int nb = 0; nb < 8; nb++) {
                int c = bn + warp_n * 64 + nb * 8 + tg * 2;
                float v0 = acc[mb][nb][hr * 2 + 0] + __ldg(&bias[c]);
                float v1 = acc[mb][nb][hr * 2 + 1] + __ldg(&bias[c + 1]);
                if (mode != 0) {
                    v0 = (v0 - __ldg(&bnm[c])) * rsqrtf(__ldg(&bnv[c]) + BN_EPS) * __ldg(&bng[c]) + __ldg(&bnb[c]);
                    v1 = (v1 - __ldg(&bnm[c + 1])) * rsqrtf(__ldg(&bnv[c + 1]) + BN_EPS) * __ldg(&bng[c + 1]) + __ldg(&bnb[c + 1]);
                    v0 = fmaxf(v0, 0.0f);
                    v1 = fmaxf(v1, 0.0f);
                }
                size_t off = (size_t)r * HID + c;
                if (mode == 1) {
                    ushort2 hp, lp;
                    split_bf16(v0, hp.x, lp.x);
                    split_bf16(v1, hp.y, lp.y);
                    *(ushort2*)(outHi + off) = hp;
                    *(ushort2*)(outLo + off) = lp;
                } else {
                    *(float2*)(outF + off) = make_float2(v0, v1);
                }
            }
        }
    }
}

// ================= fused L2 norm + BN + ELU (f32 + bf16 pair out) =================
__global__ void k_norm_bn_elu(const float* __restrict__ in, float* __restrict__ outp,
                              u16* __restrict__ hhi, u16* __restrict__ hlo,
                              const float* __restrict__ g, const float* __restrict__ b,
                              const float* __restrict__ m, const float* __restrict__ v) {
    int w = (blockIdx.x * blockDim.x + threadIdx.x) >> 5;
    int lane = threadIdx.x & 31;
    if (w >= N_NODES) return;
    const float* row = in + (size_t)w * HID;
    float vals[12];
    float ss = 0.0f;
#pragma unroll
    for (int i = 0; i < 12; i++) {
        float x = row[lane + 32 * i];
        vals[i] = x;
        ss += x * x;
    }
#pragma unroll
    for (int o = 16; o > 0; o >>= 1) ss += __shfl_xor_sync(0xffffffff, ss, o);
    float inv = 1.0f / fmaxf(sqrtf(ss), 1e-12f);
    float* orow = outp + (size_t)w * HID;
#pragma unroll
    for (int i = 0; i < 12; i++) {
        int c = lane + 32 * i;
        float x = vals[i] * inv;
        x = (x - m[c]) * rsqrtf(v[c] + BN_EPS) * g[c] + b[c];
        x = x > 0.0f ? x : expm1f(x);
        orow[c] = x;
        u16 hh, ll;
        split_bf16(x, hh, ll);
        hhi[(size_t)w * HID + c] = hh;
        hlo[(size_t)w * HID + c] = ll;
    }
}

// ================= final projection 384 -> 3 =================
__global__ void k_final(const float* __restrict__ h, const float* __restrict__ W,
                        const float* __restrict__ bias, float* __restrict__ out) {
    int w = (blockIdx.x * blockDim.x + threadIdx.x) >> 5;
    int lane = threadIdx.x & 31;
    if (w >= N_NODES) return;
    const float* row = h + (size_t)w * HID;
    float vals[12];
#pragma unroll
    for (int i = 0; i < 12; i++) vals[i] = row[lane + 32 * i];
#pragma unroll
    for (int o = 0; o < OUT_DIM; o++) {
        float s = 0.0f;
        const float* wr = W + (size_t)o * HID;
#pragma unroll
        for (int i = 0; i < 12; i++) s += vals[i] * __ldg(&wr[lane + 32 * i]);
#pragma unroll
        for (int off = 16; off > 0; off >>= 1) s += __shfl_xor_sync(0xffffffff, s, off);
        if (lane == 0) out[(size_t)w * OUT_DIM + o] = s + bias[o];
    }
}

// ================= driver =================
extern "C" void kernel_launch(void* const* d_in, const int* in_sizes, int n_in,
                              void* d_out, int out_size) {
    const float* x    = (const float*)d_in[0];
    const int*   ei   = (const int*)d_in[1];
    const float* W_l0 = (const float*)d_in[2];
    const float* b_l0 = (const float*)d_in[3];
    const float* W_r0 = (const float*)d_in[4];
    const float* W_l  = (const float*)d_in[5];
    const float* b_l  = (const float*)d_in[6];
    const float* W_r  = (const float*)d_in[7];
    const float* bn_g = (const float*)d_in[8];
    const float* bn_b = (const float*)d_in[9];
    const float* bn_m = (const float*)d_in[10];
    const float* bn_v = (const float*)d_in[11];
    const float* Wp0  = (const float*)d_in[12];
    const float* bp0  = (const float*)d_in[13];
    const float* Wp1  = (const float*)d_in[14];
    const float* bp1  = (const float*)d_in[15];
    const float* Wp2  = (const float*)d_in[16];
    const float* bp2  = (const float*)d_in[17];
    const float* pbn_g = (const float*)d_in[18];
    const float* pbn_b = (const float*)d_in[19];
    const float* pbn_m = (const float*)d_in[20];
    const float* pbn_v = (const float*)d_in[21];
    float* out = (float*)d_out;

    const int* src = ei;
    const int* dst = ei + EDGES;

    float *bufA, *bufB, *bufC, *agg10;
    int* cnt;
    u16 *whi, *wlo, *hhi, *hlo, *agh, *agl;
    cudaGetSymbolAddress((void**)&bufA, g_bufA);
    cudaGetSymbolAddress((void**)&bufB, g_bufB);
    cudaGetSymbolAddress((void**)&bufC, g_bufC);
    cudaGetSymbolAddress((void**)&agg10, g_agg10);
    cudaGetSymbolAddress((void**)&cnt, g_cnt);
    cudaGetSymbolAddress((void**)&whi, g_whi);
    cudaGetSymbolAddress((void**)&wlo, g_wlo);
    cudaGetSymbolAddress((void**)&hhi, g_hhi);
    cudaGetSymbolAddress((void**)&hlo, g_hlo);
    cudaGetSymbolAddress((void**)&agh, g_agh);
    cudaGetSymbolAddress((void**)&agl, g_agl);

    cudaFuncSetAttribute(k_mma, cudaFuncAttributeMaxDynamicSharedMemorySize, SMEM_MMA);

    const int NB = (N_NODES + 511) / 512;
    const int WSZ = HID * HID;   // 147456

    // graph preprocessing
    cudaMemsetAsync(cnt, 0, N_NODES * sizeof(int), 0);
    k_count<<<(EDGES + 255) / 256, 256>>>(dst);
    k_inv<<<(N_NODES + 255) / 256, 256>>>();
    k_scan1<<<NB, 512>>>();
    k_scan2<<<1, 32>>>(NB);
    k_scan3<<<NB, 512>>>();
    k_fill<<<(EDGES + 255) / 256, 256>>>(src, dst);

    // weight pre-split: [Wl x4 | Wr x4 | Wp0 | Wp1]
    k_conv<<<(4 * WSZ + 255) / 256, 256>>>(W_l, whi, wlo, 4 * WSZ);
    k_conv<<<(4 * WSZ + 255) / 256, 256>>>(W_r, whi + 4 * WSZ, wlo + 4 * WSZ, 4 * WSZ);
    k_conv<<<(WSZ + 255) / 256, 256>>>(Wp0, whi + 8 * WSZ, wlo + 8 * WSZ, WSZ);
    k_conv<<<(WSZ + 255) / 256, 256>>>(Wp1, whi + 9 * WSZ, wlo + 9 * WSZ, WSZ);

    const int normBlocks = (N_NODES * 32 + 255) / 256;
    dim3 ggM(3, (N_NODES + 127) / 128);
    dim3 gg0(HID / 64, (N_NODES + 127) / 128);

    // ---- layer 0 (K=10, SIMT) ----
    k_gather10<<<(N_NODES + 255) / 256, 256>>>(x, agg10);
    k_gemm<<<gg0, 256>>>(agg10, W_l0, x, W_r0, b_l0, bufC, N_NODES, IN_DIM, HID);
    k_norm_bn_elu<<<normBlocks, 256>>>(bufC, bufA, hhi, hlo, bn_g, bn_b, bn_m, bn_v);

    // ---- layers 1..4 (HMMA, pre-split) ----
    for (int t = 1; t < 5; t++) {
        k_gather384<<<(N_NODES + 7) / 8, 256>>>(bufA, agh, agl);
        const u16* wlh = whi + (size_t)(t - 1) * WSZ;
        const u16* wll = wlo + (size_t)(t - 1) * WSZ;
        const u16* wrh = whi + (size_t)(4 + t - 1) * WSZ;
        const u16* wrl = wlo + (size_t)(4 + t - 1) * WSZ;
        const float* bl = b_l + (size_t)(t - 1) * HID;
        k_mma<<<ggM, 256, SMEM_MMA>>>(agh, agl, wlh, wll, hhi, hlo, wrh, wrl,
                                      bl, bufC, nullptr, nullptr, 0,
                                      nullptr, nullptr, nullptr, nullptr);
        k_norm_bn_elu<<<normBlocks, 256>>>(bufC, bufA, hhi, hlo,
                                           bn_g + t * HID, bn_b + t * HID,
                                           bn_m + t * HID, bn_v + t * HID);
    }

    // ---- projection MLP ----
    // proj0: in = h pair, out = bf16 pair (agh/agl reused)
    k_mma<<<ggM, 256, SMEM_MMA>>>(hhi, hlo, whi + 8 * WSZ, wlo + 8 * WSZ,
                                  nullptr, nullptr, nullptr, nullptr,
                                  bp0, nullptr, agh, agl, 1,
                                  pbn_g, pbn_b, pbn_m, pbn_v);
    // proj1: in = pair, out = f32 bufB
    k_mma<<<ggM, 256, SMEM_MMA>>>(agh, agl, whi + 9 * WSZ, wlo + 9 * WSZ,
                                  nullptr, nullptr, nullptr, nullptr,
                                  bp1, bufB, nullptr, nullptr, 2,
                                  pbn_g + HID, pbn_b + HID, pbn_m + HID, pbn_v + HID);
    k_final<<<normBlocks, 256>>>(bufB, Wp2, bp2, out);
}

// round 14
// speedup vs baseline: 2.9891x; 1.1125x over previous
#include <cuda_runtime.h>
#include <cuda_bf16.h>
#include <math.h>
#include <stdint.h>

#define N_NODES 100000
#define EDGES   300000
#define IN_DIM  10
#define HID     384
#define OUT_DIM 3
#define BN_EPS  1e-5f

typedef unsigned short u16;

// ---------------- scratch (no allocs allowed) ----------------
__device__ float g_bufA[(size_t)N_NODES * HID];   // h post-norm (f32, for gather)
__device__ float g_bufB[(size_t)N_NODES * HID];   // proj1 out (f32)
__device__ float g_bufC[(size_t)N_NODES * HID];   // GEMM out (f32, pre-norm)
__device__ float g_agg10[(size_t)N_NODES * IN_DIM];
__device__ float g_inv[N_NODES];
__device__ int   g_cnt[N_NODES];
__device__ int   g_off[N_NODES + 1];
__device__ int   g_cur[N_NODES];
__device__ int   g_csr[EDGES];
__device__ int   g_bsum[256];
// bf16 hi/lo pre-split operands
__device__ u16 g_whi[10 * HID * HID];
__device__ u16 g_wlo[10 * HID * HID];
__device__ u16 g_hhi[(size_t)N_NODES * HID];
__device__ u16 g_hlo[(size_t)N_NODES * HID];
__device__ u16 g_agh[(size_t)N_NODES * HID];
__device__ u16 g_agl[(size_t)N_NODES * HID];

// ================= helpers =================
__device__ __forceinline__ uint32_t smem_u32(const void* p) {
    uint32_t a;
    asm("{ .reg .u64 t; cvta.to.shared.u64 t, %1; cvt.u32.u64 %0, t; }" : "=r"(a) : "l"(p));
    return a;
}
__device__ __forceinline__ void split_bf16(float v, u16& h, u16& l) {
    __nv_bfloat16 hb = __float2bfloat16(v);
    h = __bfloat16_as_ushort(hb);
    l = __bfloat16_as_ushort(__float2bfloat16(v - __bfloat162float(hb)));
}
__device__ __forceinline__ void cpasync16(uint32_t dst, const void* src, int nbytes) {
    asm volatile("cp.async.ca.shared.global [%0], [%1], 16, %2;"
                 :: "r"(dst), "l"(src), "r"(nbytes) : "memory");
}

#define LDM4(r, a) \
    asm volatile("ldmatrix.sync.aligned.m8n8.x4.shared.b16 {%0,%1,%2,%3}, [%4];" \
        : "=r"((r)[0]), "=r"((r)[1]), "=r"((r)[2]), "=r"((r)[3]) : "r"(a))

#define MMA16816(c, a, b0, b1) \
    asm volatile("mma.sync.aligned.m16n8k16.row.col.f32.bf16.bf16.f32 " \
        "{%0,%1,%2,%3},{%4,%5,%6,%7},{%8,%9},{%0,%1,%2,%3};" \
        : "+f"((c)[0]), "+f"((c)[1]), "+f"((c)[2]), "+f"((c)[3]) \
        : "r"((a)[0]), "r"((a)[1]), "r"((a)[2]), "r"((a)[3]), "r"(b0), "r"(b1))

// ================= graph preprocessing =================
__global__ void k_count(const int* __restrict__ dst) {
    int i = blockIdx.x * blockDim.x + threadIdx.x;
    if (i < EDGES) atomicAdd(&g_cnt[dst[i]], 1);
}
__global__ void k_inv() {
    int i = blockIdx.x * blockDim.x + threadIdx.x;
    if (i < N_NODES) g_inv[i] = 1.0f / fmaxf((float)g_cnt[i], 1.0f);
}
__global__ void k_scan1() {
    __shared__ int s[512];
    int idx = blockIdx.x * 512 + threadIdx.x;
    int v = (idx < N_NODES) ? g_cnt[idx] : 0;
    s[threadIdx.x] = v;
    __syncthreads();
    for (int o = 1; o < 512; o <<= 1) {
        int t = (threadIdx.x >= o) ? s[threadIdx.x - o] : 0;
        __syncthreads();
        s[threadIdx.x] += t;
        __syncthreads();
    }
    if (idx < N_NODES) g_off[idx] = s[threadIdx.x] - v;
    if (threadIdx.x == 511) g_bsum[blockIdx.x] = s[511];
}
__global__ void k_scan2(int nb) {
    if (threadIdx.x == 0) {
        int run = 0;
        for (int i = 0; i < nb; i++) { int t = g_bsum[i]; g_bsum[i] = run; run += t; }
    }
}
__global__ void k_scan3() {
    int idx = blockIdx.x * 512 + threadIdx.x;
    if (idx < N_NODES) {
        int o = g_off[idx] + g_bsum[blockIdx.x];
        g_off[idx] = o;
        g_cur[idx] = o;
    }
    if (idx == 0) g_off[N_NODES] = EDGES;
}
__global__ void k_fill(const int* __restrict__ src, const int* __restrict__ dst) {
    int e = blockIdx.x * blockDim.x + threadIdx.x;
    if (e < EDGES) {
        int p = atomicAdd(&g_cur[dst[e]], 1);
        g_csr[p] = src[e];
    }
}

// ================= weight pre-split =================
__global__ void k_conv(const float* __restrict__ src, u16* __restrict__ hi,
                       u16* __restrict__ lo, int n) {
    int i = blockIdx.x * blockDim.x + threadIdx.x;
    if (i < n) {
        u16 h, l;
        split_bf16(src[i], h, l);
        hi[i] = h;
        lo[i] = l;
    }
}

// ================= mean aggregation (CSR gather) =================
__global__ void k_gather10(const float* __restrict__ x, float* __restrict__ agg) {
    int n = blockIdx.x * blockDim.x + threadIdx.x;
    if (n >= N_NODES) return;
    float acc[IN_DIM];
#pragma unroll
    for (int c = 0; c < IN_DIM; c++) acc[c] = 0.0f;
    int beg = g_off[n], end = g_off[n + 1];
    for (int e = beg; e < end; e++) {
        const float* r = x + (size_t)g_csr[e] * IN_DIM;
#pragma unroll
        for (int c = 0; c < IN_DIM; c++) acc[c] += __ldg(&r[c]);
    }
    float iv = g_inv[n];
#pragma unroll
    for (int c = 0; c < IN_DIM; c++) agg[(size_t)n * IN_DIM + c] = acc[c] * iv;
}

// gather h (f32) -> agg as bf16 hi/lo pair
__global__ void k_gather384(const float* __restrict__ h,
                            u16* __restrict__ aggh, u16* __restrict__ aggl) {
    int n = blockIdx.x * 8 + (threadIdx.x >> 5);
    int lane = threadIdx.x & 31;
    if (n >= N_NODES) return;
    int beg = g_off[n], end = g_off[n + 1];
    float4 a0 = make_float4(0, 0, 0, 0), a1 = a0, a2 = a0;
    for (int e = beg; e < end; e++) {
        const float4* r = (const float4*)(h + (size_t)g_csr[e] * HID) + lane;
        float4 v0 = r[0], v1 = r[32], v2 = r[64];
        a0.x += v0.x; a0.y += v0.y; a0.z += v0.z; a0.w += v0.w;
        a1.x += v1.x; a1.y += v1.y; a1.z += v1.z; a1.w += v1.w;
        a2.x += v2.x; a2.y += v2.y; a2.z += v2.z; a2.w += v2.w;
    }
    float iv = g_inv[n];
    float g4[3][4] = {{a0.x * iv, a0.y * iv, a0.z * iv, a0.w * iv},
                      {a1.x * iv, a1.y * iv, a1.z * iv, a1.w * iv},
                      {a2.x * iv, a2.y * iv, a2.z * iv, a2.w * iv}};
#pragma unroll
    for (int g = 0; g < 3; g++) {
        ushort4 hv, lv;
        split_bf16(g4[g][0], hv.x, lv.x);
        split_bf16(g4[g][1], hv.y, lv.y);
        split_bf16(g4[g][2], hv.z, lv.z);
        split_bf16(g4[g][3], hv.w, lv.w);
        size_t off = (size_t)n * HID + g * 128 + lane * 4;
        *(ushort4*)(aggh + off) = hv;
        *(ushort4*)(aggl + off) = lv;
    }
}

// ================= SIMT GEMM (layer 0 only, K=10) =================
__global__ __launch_bounds__(256)
void k_gemm(const float* __restrict__ A0, const float* __restrict__ W0,
            const float* __restrict__ A1, const float* __restrict__ W1,
            const float* __restrict__ bias,
            float* __restrict__ out, int M, int K, int NC) {
    __shared__ float As[8][132];
    __shared__ float Bs[8][68];
    int tid = threadIdx.x;
    int ty = tid >> 4, tx = tid & 15;
    int bm = blockIdx.y * 128, bn = blockIdx.x * 64;

    float acc[8][4];
#pragma unroll
    for (int i = 0; i < 8; i++)
#pragma unroll
        for (int j = 0; j < 4; j++) acc[i][j] = 0.0f;

    int idA = tid * 4, am = idA >> 3, ak = idA & 7;
    int idB = tid * 2, bj = idB >> 3, bk = idB & 7;

#pragma unroll 1
    for (int pass = 0; pass < 2; pass++) {
        const float* A = pass ? A1 : A0;
        const float* W = pass ? W1 : W0;
        if (A == nullptr) continue;
        for (int k0 = 0; k0 < K; k0 += 8) {
            {
                const float* ap = A + (size_t)(bm + am) * K + k0 + ak;
                bool rok = (bm + am) < M;
#pragma unroll
                for (int i = 0; i < 4; i++) {
                    float v = 0.0f;
                    if (rok && (k0 + ak + i) < K) v = ap[i];
                    As[ak + i][am] = v;
                }
            }
            {
#pragma unroll
                for (int i = 0; i < 2; i++) {
                    float v = 0.0f;
                    int col = bn + bj, kk = k0 + bk + i;
                    if (col < NC && kk < K) v = W[(size_t)col * K + kk];
                    Bs[bk + i][bj] = v;
                }
            }
            __syncthreads();
#pragma unroll
            for (int k = 0; k < 8; k++) {
                float a[8], b[4];
#pragma unroll
                for (int i = 0; i < 8; i++) a[i] = As[k][ty * 8 + i];
#pragma unroll
                for (int j = 0; j < 4; j++) b[j] = Bs[k][tx * 4 + j];
#pragma unroll
                for (int i = 0; i < 8; i++)
#pragma unroll
                    for (int j = 0; j < 4; j++) acc[i][j] = fmaf(a[i], b[j], acc[i][j]);
            }
            __syncthreads();
        }
    }
#pragma unroll
    for (int i = 0; i < 8; i++) {
        int r = bm + ty * 8 + i;
        if (r >= M) continue;
#pragma unroll
        for (int j = 0; j < 4; j++) {
            int c = bn + tx * 4 + j;
            if (c >= NC) continue;
            out[(size_t)r * NC + c] = acc[i][j] + bias[c];
        }
    }
}

// ================= HMMA GEMM, pre-split bf16, cp.async, 2 CTAs/SM =================
// mode 0: out = f32 (bias only); mode 1: BN+ReLU -> bf16 pair; mode 2: BN+ReLU -> f32
#define MM_STRIDE 80
#define MM_TILE   (128 * MM_STRIDE)
#define OFF_AH    0
#define OFF_AL    (1 * MM_TILE)
#define OFF_BH    (2 * MM_TILE)
#define OFF_BL    (3 * MM_TILE)
#define STAGE_B   (4 * MM_TILE)
#define SMEM_MMA  (2 * STAGE_B)

__global__ __launch_bounds__(256, 2)
void k_mma(const u16* __restrict__ A0h, const u16* __restrict__ A0l,
           const u16* __restrict__ W0h, const u16* __restrict__ W0l,
           const u16* __restrict__ A1h, const u16* __restrict__ A1l,
           const u16* __restrict__ W1h, const u16* __restrict__ W1l,
           const float* __restrict__ bias, float* __restrict__ outF,
           u16* __restrict__ outHi, u16* __restrict__ outLo, int mode,
           const float* __restrict__ bng, const float* __restrict__ bnb,
           const float* __restrict__ bnm, const float* __restrict__ bnv) {
    extern __shared__ char sm[];
    const int M = N_NODES;
    int tid = threadIdx.x, lane = tid & 31, wid = tid >> 5;
    int bm = blockIdx.y * 128, bn = blockIdx.x * 128;
    int warp_m = wid & 3, warp_n = wid >> 2;

    float acc[2][8][4];
#pragma unroll
    for (int mb = 0; mb < 2; mb++)
#pragma unroll
        for (int nb = 0; nb < 8; nb++)
#pragma unroll
            for (int q = 0; q < 4; q++) acc[mb][nb][q] = 0.0f;

    int lrow = tid >> 1, half = tid & 1;
    bool aok = (bm + lrow) < M;
    int abytes = aok ? 16 : 0;
    const int nsrc = (A1h != nullptr) ? 2 : 1;
    const int nch = nsrc * 12;

    uint32_t smb = smem_u32(sm);
    uint32_t ldst = smb + (uint32_t)lrow * MM_STRIDE + half * 32;

    // async-load one 32-k chunk (4 tiles) into a stage
    auto load_stage = [&](int ch, int stage) {
        int s = (ch < 12) ? 0 : 1;
        const u16* Ah = s ? A1h : A0h;
        const u16* Al = s ? A1l : A0l;
        const u16* Bh = s ? W1h : W0h;
        const u16* Bl = s ? W1l : W0l;
        int k0 = (ch - s * 12) * 32;
        size_t ao = aok ? ((size_t)(bm + lrow) * HID + k0 + half * 16) : 0;
        size_t bo = (size_t)(bn + lrow) * HID + k0 + half * 16;
        uint32_t d = ldst + stage * STAGE_B;
        cpasync16(d + OFF_AH,      Ah + ao,     abytes);
        cpasync16(d + OFF_AH + 16, Ah + ao + 8, abytes);
        cpasync16(d + OFF_AL,      Al + ao,     abytes);
        cpasync16(d + OFF_AL + 16, Al + ao + 8, abytes);
        cpasync16(d + OFF_BH,      Bh + bo,     16);
        cpasync16(d + OFF_BH + 16, Bh + bo + 8, 16);
        cpasync16(d + OFF_BL,      Bl + bo,     16);
        cpasync16(d + OFF_BL + 16, Bl + bo + 8, 16);
        asm volatile("cp.async.commit_group;" ::: "memory");
    };

    int l15 = lane & 15, kh = lane >> 4;
    uint32_t aoff = (uint32_t)(warp_m * 32 + l15) * MM_STRIDE + kh * 16;
    uint32_t boff = (uint32_t)(warp_n * 64 + l15) * MM_STRIDE + kh * 16;

    auto mmastage = [&](int stage) {
        uint32_t sb = smb + stage * STAGE_B;
#pragma unroll
        for (int s = 0; s < 2; s++) {
            uint32_t ko = s * 32;
            uint32_t ahf[2][4], alf[2][4], bhf[4][4], blf[4][4];
#pragma unroll
            for (int mb = 0; mb < 2; mb++) {
                LDM4(ahf[mb], sb + OFF_AH + aoff + mb * (16 * MM_STRIDE) + ko);
                LDM4(alf[mb], sb + OFF_AL + aoff + mb * (16 * MM_STRIDE) + ko);
            }
#pragma unroll
            for (int pb = 0; pb < 4; pb++) {
                LDM4(bhf[pb], sb + OFF_BH + boff + pb * (16 * MM_STRIDE) + ko);
                LDM4(blf[pb], sb + OFF_BL + boff + pb * (16 * MM_STRIDE) + ko);
            }
#pragma unroll
            for (int mb = 0; mb < 2; mb++)
#pragma unroll
                for (int nb = 0; nb < 8; nb++) {
                    int pb = nb >> 1, sel = nb & 1;
                    MMA16816(acc[mb][nb], ahf[mb], bhf[pb][sel], bhf[pb][sel + 2]);
                    MMA16816(acc[mb][nb], ahf[mb], blf[pb][sel], blf[pb][sel + 2]);
                    MMA16816(acc[mb][nb], alf[mb], bhf[pb][sel], bhf[pb][sel + 2]);
                }
        }
    };

    load_stage(0, 0);
#pragma unroll 1
    for (int ch = 0; ch < nch; ch++) {
        __syncthreads();   // all warps done reading the stage about to be overwritten
        if (ch + 1 < nch) {
            load_stage(ch + 1, (ch + 1) & 1);
            asm volatile("cp.async.wait_group 1;" ::: "memory");
        } else {
            asm volatile("cp.async.wait_group 0;" ::: "memory");
        }
        __syncthreads();   // current stage visible to all warps
        mmastage(ch & 1);
    }

    // epilogue
    int g = lane >> 2, tg = lane & 3;
#pragma unroll
    for (int mb = 0; mb < 2; mb++) {
#pragma unroll
        for (int hr = 0; hr < 2; hr++) {
            int r = bm + warp_m * 32 + mb * 16 + g + hr * 8;
            if (r >= M) continue;
#pragma unroll
            for (int nb = 0; nb < 8; nb++) {
                int c = bn + warp_n * 64 + nb * 8 + tg * 2;
                float v0 = acc[mb][nb][hr * 2 + 0] + __ldg(&bias[c]);
                float v1 = acc[mb][nb][hr * 2 + 1] + __ldg(&bias[c + 1]);
                if (mode != 0) {
                    v0 = (v0 - __ldg(&bnm[c])) * rsqrtf(__ldg(&bnv[c]) + BN_EPS) * __ldg(&bng[c]) + __ldg(&bnb[c]);
                    v1 = (v1 - __ldg(&bnm[c + 1])) * rsqrtf(__ldg(&bnv[c + 1]) + BN_EPS) * __ldg(&bng[c + 1]) + __ldg(&bnb[c + 1]);
                    v0 = fmaxf(v0, 0.0f);
                    v1 = fmaxf(v1, 0.0f);
                }
                size_t off = (size_t)r * HID + c;
                if (mode == 1) {
                    ushort2 hp, lp;
                    split_bf16(v0, hp.x, lp.x);
                    split_bf16(v1, hp.y, lp.y);
                    *(ushort2*)(outHi + off) = hp;
                    *(ushort2*)(outLo + off) = lp;
                } else {
                    *(float2*)(outF + off) = make_float2(v0, v1);
                }
            }
        }
    }
}

// ================= fused L2 norm + BN + ELU (f32 + bf16 pair out) =================
__global__ void k_norm_bn_elu(const float* __restrict__ in, float* __restrict__ outp,
                              u16* __restrict__ hhi, u16* __restrict__ hlo,
                              const float* __restrict__ g, const float* __restrict__ b,
                              const float* __restrict__ m, const float* __restrict__ v) {
    int w = (blockIdx.x * blockDim.x + threadIdx.x) >> 5;
    int lane = threadIdx.x & 31;
    if (w >= N_NODES) return;
    const float* row = in + (size_t)w * HID;
    float vals[12];
    float ss = 0.0f;
#pragma unroll
    for (int i = 0; i < 12; i++) {
        float x = row[lane + 32 * i];
        vals[i] = x;
        ss += x * x;
    }
#pragma unroll
    for (int o = 16; o > 0; o >>= 1) ss += __shfl_xor_sync(0xffffffff, ss, o);
    float inv = 1.0f / fmaxf(sqrtf(ss), 1e-12f);
    float* orow = outp + (size_t)w * HID;
#pragma unroll
    for (int i = 0; i < 12; i++) {
        int c = lane + 32 * i;
        float x = vals[i] * inv;
        x = (x - m[c]) * rsqrtf(v[c] + BN_EPS) * g[c] + b[c];
        x = x > 0.0f ? x : expm1f(x);
        orow[c] = x;
        u16 hh, ll;
        split_bf16(x, hh, ll);
        hhi[(size_t)w * HID + c] = hh;
        hlo[(size_t)w * HID + c] = ll;
    }
}

// ================= final projection 384 -> 3 =================
__global__ void k_final(const float* __restrict__ h, const float* __restrict__ W,
                        const float* __restrict__ bias, float* __restrict__ out) {
    int w = (blockIdx.x * blockDim.x + threadIdx.x) >> 5;
    int lane = threadIdx.x & 31;
    if (w >= N_NODES) return;
    const float* row = h + (size_t)w * HID;
    float vals[12];
#pragma unroll
    for (int i = 0; i < 12; i++) vals[i] = row[lane + 32 * i];
#pragma unroll
    for (int o = 0; o < OUT_DIM; o++) {
        float s = 0.0f;
        const float* wr = W + (size_t)o * HID;
#pragma unroll
        for (int i = 0; i < 12; i++) s += vals[i] * __ldg(&wr[lane + 32 * i]);
#pragma unroll
        for (int off = 16; off > 0; off >>= 1) s += __shfl_xor_sync(0xffffffff, s, off);
        if (lane == 0) out[(size_t)w * OUT_DIM + o] = s + bias[o];
    }
}

// ================= driver =================
extern "C" void kernel_launch(void* const* d_in, const int* in_sizes, int n_in,
                              void* d_out, int out_size) {
    const float* x    = (const float*)d_in[0];
    const int*   ei   = (const int*)d_in[1];
    const float* W_l0 = (const float*)d_in[2];
    const float* b_l0 = (const float*)d_in[3];
    const float* W_r0 = (const float*)d_in[4];
    const float* W_l  = (const float*)d_in[5];
    const float* b_l  = (const float*)d_in[6];
    const float* W_r  = (const float*)d_in[7];
    const float* bn_g = (const float*)d_in[8];
    const float* bn_b = (const float*)d_in[9];
    const float* bn_m = (const float*)d_in[10];
    const float* bn_v = (const float*)d_in[11];
    const float* Wp0  = (const float*)d_in[12];
    const float* bp0  = (const float*)d_in[13];
    const float* Wp1  = (const float*)d_in[14];
    const float* bp1  = (const float*)d_in[15];
    const float* Wp2  = (const float*)d_in[16];
    const float* bp2  = (const float*)d_in[17];
    const float* pbn_g = (const float*)d_in[18];
    const float* pbn_b = (const float*)d_in[19];
    const float* pbn_m = (const float*)d_in[20];
    const float* pbn_v = (const float*)d_in[21];
    float* out = (float*)d_out;

    const int* src = ei;
    const int* dst = ei + EDGES;

    float *bufA, *bufB, *bufC, *agg10;
    int* cnt;
    u16 *whi, *wlo, *hhi, *hlo, *agh, *agl;
    cudaGetSymbolAddress((void**)&bufA, g_bufA);
    cudaGetSymbolAddress((void**)&bufB, g_bufB);
    cudaGetSymbolAddress((void**)&bufC, g_bufC);
    cudaGetSymbolAddress((void**)&agg10, g_agg10);
    cudaGetSymbolAddress((void**)&cnt, g_cnt);
    cudaGetSymbolAddress((void**)&whi, g_whi);
    cudaGetSymbolAddress((void**)&wlo, g_wlo);
    cudaGetSymbolAddress((void**)&hhi, g_hhi);
    cudaGetSymbolAddress((void**)&hlo, g_hlo);
    cudaGetSymbolAddress((void**)&agh, g_agh);
    cudaGetSymbolAddress((void**)&agl, g_agl);

    cudaFuncSetAttribute(k_mma, cudaFuncAttributeMaxDynamicSharedMemorySize, SMEM_MMA);

    const int NB = (N_NODES + 511) / 512;
    const int WSZ = HID * HID;   // 147456

    // graph preprocessing
    cudaMemsetAsync(cnt, 0, N_NODES * sizeof(int), 0);
    k_count<<<(EDGES + 255) / 256, 256>>>(dst);
    k_inv<<<(N_NODES + 255) / 256, 256>>>();
    k_scan1<<<NB, 512>>>();
    k_scan2<<<1, 32>>>(NB);
    k_scan3<<<NB, 512>>>();
    k_fill<<<(EDGES + 255) / 256, 256>>>(src, dst);

    // weight pre-split: [Wl x4 | Wr x4 | Wp0 | Wp1]
    k_conv<<<(4 * WSZ + 255) / 256, 256>>>(W_l, whi, wlo, 4 * WSZ);
    k_conv<<<(4 * WSZ + 255) / 256, 256>>>(W_r, whi + 4 * WSZ, wlo + 4 * WSZ, 4 * WSZ);
    k_conv<<<(WSZ + 255) / 256, 256>>>(Wp0, whi + 8 * WSZ, wlo + 8 * WSZ, WSZ);
    k_conv<<<(WSZ + 255) / 256, 256>>>(Wp1, whi + 9 * WSZ, wlo + 9 * WSZ, WSZ);

    const int normBlocks = (N_NODES * 32 + 255) / 256;
    dim3 ggM(3, (N_NODES + 127) / 128);
    dim3 gg0(HID / 64, (N_NODES + 127) / 128);

    // ---- layer 0 (K=10, SIMT) ----
    k_gather10<<<(N_NODES + 255) / 256, 256>>>(x, agg10);
    k_gemm<<<gg0, 256>>>(agg10, W_l0, x, W_r0, b_l0, bufC, N_NODES, IN_DIM, HID);
    k_norm_bn_elu<<<normBlocks, 256>>>(bufC, bufA, hhi, hlo, bn_g, bn_b, bn_m, bn_v);

    // ---- layers 1..4 (HMMA, pre-split) ----
    for (int t = 1; t < 5; t++) {
        k_gather384<<<(N_NODES + 7) / 8, 256>>>(bufA, agh, agl);
        const u16* wlh = whi + (size_t)(t - 1) * WSZ;
        const u16* wll = wlo + (size_t)(t - 1) * WSZ;
        const u16* wrh = whi + (size_t)(4 + t - 1) * WSZ;
        const u16* wrl = wlo + (size_t)(4 + t - 1) * WSZ;
        const float* bl = b_l + (size_t)(t - 1) * HID;
        k_mma<<<ggM, 256, SMEM_MMA>>>(agh, agl, wlh, wll, hhi, hlo, wrh, wrl,
                                      bl, bufC, nullptr, nullptr, 0,
                                      nullptr, nullptr, nullptr, nullptr);
        k_norm_bn_elu<<<normBlocks, 256>>>(bufC, bufA, hhi, hlo,
                                           bn_g + t * HID, bn_b + t * HID,
                                           bn_m + t * HID, bn_v + t * HID);
    }

    // ---- projection MLP ----
    // proj0: in = h pair, out = bf16 pair (agh/agl reused)
    k_mma<<<ggM, 256, SMEM_MMA>>>(hhi, hlo, whi + 8 * WSZ, wlo + 8 * WSZ,
                                  nullptr, nullptr, nullptr, nullptr,
                                  bp0, nullptr, agh, agl, 1,
                                  pbn_g, pbn_b, pbn_m, pbn_v);
    // proj1: in = pair, out = f32 bufB
    k_mma<<<ggM, 256, SMEM_MMA>>>(agh, agl, whi + 9 * WSZ, wlo + 9 * WSZ,
                                  nullptr, nullptr, nullptr, nullptr,
                                  bp1, bufB, nullptr, nullptr, 2,
                                  pbn_g + HID, pbn_b + HID, pbn_m + HID, pbn_v + HID);
    k_final<<<normBlocks, 256>>>(bufB, Wp2, bp2, out);
}

// round 15
// speedup vs baseline: 3.0286x; 1.0132x over previous
#include <cuda_runtime.h>
#include <cuda_bf16.h>
#include <math.h>
#include <stdint.h>

#define N_NODES 100000
#define EDGES   300000
#define IN_DIM  10
#define HID     384
#define OUT_DIM 3
#define BN_EPS  1e-5f

typedef unsigned short u16;

// ---------------- scratch (no allocs allowed) ----------------
__device__ float g_bufB[(size_t)N_NODES * HID];   // proj1 out (f32)
__device__ float g_bufC[(size_t)N_NODES * HID];   // GEMM out (f32, pre-norm)
__device__ float g_agg10[(size_t)N_NODES * IN_DIM];
__device__ float g_inv[N_NODES];
__device__ int   g_cnt[N_NODES];
__device__ int   g_off[N_NODES + 1];
__device__ int   g_cur[N_NODES];
__device__ int   g_csr[EDGES];
__device__ int   g_bsum[256];
// bf16 hi/lo pre-split operands
__device__ u16 g_whi[10 * HID * HID];
__device__ u16 g_wlo[10 * HID * HID];
__device__ u16 g_hhi[(size_t)N_NODES * HID];
__device__ u16 g_hlo[(size_t)N_NODES * HID];
__device__ u16 g_agh[(size_t)N_NODES * HID];
__device__ u16 g_agl[(size_t)N_NODES * HID];

// ================= helpers =================
__device__ __forceinline__ uint32_t smem_u32(const void* p) {
    uint32_t a;
    asm("{ .reg .u64 t; cvta.to.shared.u64 t, %1; cvt.u32.u64 %0, t; }" : "=r"(a) : "l"(p));
    return a;
}
__device__ __forceinline__ void split_bf16(float v, u16& h, u16& l) {
    __nv_bfloat16 hb = __float2bfloat16(v);
    h = __bfloat16_as_ushort(hb);
    l = __bfloat16_as_ushort(__float2bfloat16(v - __bfloat162float(hb)));
}
__device__ __forceinline__ float bf16_pair(u16 h, u16 l) {
    return __uint_as_float((uint32_t)h << 16) + __uint_as_float((uint32_t)l << 16);
}
__device__ __forceinline__ void cpasync16(uint32_t dst, const void* src, int nbytes) {
    asm volatile("cp.async.ca.shared.global [%0], [%1], 16, %2;"
                 :: "r"(dst), "l"(src), "r"(nbytes) : "memory");
}

#define LDM4(r, a) \
    asm volatile("ldmatrix.sync.aligned.m8n8.x4.shared.b16 {%0,%1,%2,%3}, [%4];" \
        : "=r"((r)[0]), "=r"((r)[1]), "=r"((r)[2]), "=r"((r)[3]) : "r"(a))

#define MMA16816(c, a, b0, b1) \
    asm volatile("mma.sync.aligned.m16n8k16.row.col.f32.bf16.bf16.f32 " \
        "{%0,%1,%2,%3},{%4,%5,%6,%7},{%8,%9},{%0,%1,%2,%3};" \
        : "+f"((c)[0]), "+f"((c)[1]), "+f"((c)[2]), "+f"((c)[3]) \
        : "r"((a)[0]), "r"((a)[1]), "r"((a)[2]), "r"((a)[3]), "r"(b0), "r"(b1))

// ================= graph preprocessing =================
__global__ void k_count(const int* __restrict__ dst) {
    int i = blockIdx.x * blockDim.x + threadIdx.x;
    if (i < EDGES) atomicAdd(&g_cnt[dst[i]], 1);
}
__global__ void k_inv() {
    int i = blockIdx.x * blockDim.x + threadIdx.x;
    if (i < N_NODES) g_inv[i] = 1.0f / fmaxf((float)g_cnt[i], 1.0f);
}
__global__ void k_scan1() {
    __shared__ int s[512];
    int idx = blockIdx.x * 512 + threadIdx.x;
    int v = (idx < N_NODES) ? g_cnt[idx] : 0;
    s[threadIdx.x] = v;
    __syncthreads();
    for (int o = 1; o < 512; o <<= 1) {
        int t = (threadIdx.x >= o) ? s[threadIdx.x - o] : 0;
        __syncthreads();
        s[threadIdx.x] += t;
        __syncthreads();
    }
    if (idx < N_NODES) g_off[idx] = s[threadIdx.x] - v;
    if (threadIdx.x == 511) g_bsum[blockIdx.x] = s[511];
}
__global__ void k_scan2(int nb) {
    if (threadIdx.x == 0) {
        int run = 0;
        for (int i = 0; i < nb; i++) { int t = g_bsum[i]; g_bsum[i] = run; run += t; }
    }
}
__global__ void k_scan3() {
    int idx = blockIdx.x * 512 + threadIdx.x;
    if (idx < N_NODES) {
        int o = g_off[idx] + g_bsum[blockIdx.x];
        g_off[idx] = o;
        g_cur[idx] = o;
    }
    if (idx == 0) g_off[N_NODES] = EDGES;
}
__global__ void k_fill(const int* __restrict__ src, const int* __restrict__ dst) {
    int e = blockIdx.x * blockDim.x + threadIdx.x;
    if (e < EDGES) {
        int p = atomicAdd(&g_cur[dst[e]], 1);
        g_csr[p] = src[e];
    }
}

// ================= weight pre-split =================
__global__ void k_conv(const float* __restrict__ src, u16* __restrict__ hi,
                       u16* __restrict__ lo, int n) {
    int i = blockIdx.x * blockDim.x + threadIdx.x;
    if (i < n) {
        u16 h, l;
        split_bf16(src[i], h, l);
        hi[i] = h;
        lo[i] = l;
    }
}

// ================= mean aggregation (CSR gather) =================
__global__ void k_gather10(const float* __restrict__ x, float* __restrict__ agg) {
    int n = blockIdx.x * blockDim.x + threadIdx.x;
    if (n >= N_NODES) return;
    float acc[IN_DIM];
#pragma unroll
    for (int c = 0; c < IN_DIM; c++) acc[c] = 0.0f;
    int beg = g_off[n], end = g_off[n + 1];
    for (int e = beg; e < end; e++) {
        const float* r = x + (size_t)g_csr[e] * IN_DIM;
#pragma unroll
        for (int c = 0; c < IN_DIM; c++) acc[c] += __ldg(&r[c]);
    }
    float iv = g_inv[n];
#pragma unroll
    for (int c = 0; c < IN_DIM; c++) agg[(size_t)n * IN_DIM + c] = acc[c] * iv;
}

// gather h (bf16 hi/lo pairs) -> agg as bf16 hi/lo pair
__global__ void k_gather384(const u16* __restrict__ hhi, const u16* __restrict__ hlo,
                            u16* __restrict__ aggh, u16* __restrict__ aggl) {
    int n = blockIdx.x * 8 + (threadIdx.x >> 5);
    int lane = threadIdx.x & 31;
    if (n >= N_NODES) return;
    int beg = g_off[n], end = g_off[n + 1];
    float acc[3][4];
#pragma unroll
    for (int g = 0; g < 3; g++)
#pragma unroll
        for (int q = 0; q < 4; q++) acc[g][q] = 0.0f;
    for (int e = beg; e < end; e++) {
        size_t rb = (size_t)g_csr[e] * HID + lane * 4;
#pragma unroll
        for (int g = 0; g < 3; g++) {
            ushort4 hv = *(const ushort4*)(hhi + rb + g * 128);
            ushort4 lv = *(const ushort4*)(hlo + rb + g * 128);
            acc[g][0] += bf16_pair(hv.x, lv.x);
            acc[g][1] += bf16_pair(hv.y, lv.y);
            acc[g][2] += bf16_pair(hv.z, lv.z);
            acc[g][3] += bf16_pair(hv.w, lv.w);
        }
    }
    float iv = g_inv[n];
#pragma unroll
    for (int g = 0; g < 3; g++) {
        ushort4 hv, lv;
        split_bf16(acc[g][0] * iv, hv.x, lv.x);
        split_bf16(acc[g][1] * iv, hv.y, lv.y);
        split_bf16(acc[g][2] * iv, hv.z, lv.z);
        split_bf16(acc[g][3] * iv, hv.w, lv.w);
        size_t off = (size_t)n * HID + g * 128 + lane * 4;
        *(ushort4*)(aggh + off) = hv;
        *(ushort4*)(aggl + off) = lv;
    }
}

// ================= SIMT GEMM (layer 0 only, K=10) =================
__global__ __launch_bounds__(256)
void k_gemm(const float* __restrict__ A0, const float* __restrict__ W0,
            const float* __restrict__ A1, const float* __restrict__ W1,
            const float* __restrict__ bias,
            float* __restrict__ out, int M, int K, int NC) {
    __shared__ float As[8][132];
    __shared__ float Bs[8][68];
    int tid = threadIdx.x;
    int ty = tid >> 4, tx = tid & 15;
    int bm = blockIdx.y * 128, bn = blockIdx.x * 64;

    float acc[8][4];
#pragma unroll
    for (int i = 0; i < 8; i++)
#pragma unroll
        for (int j = 0; j < 4; j++) acc[i][j] = 0.0f;

    int idA = tid * 4, am = idA >> 3, ak = idA & 7;
    int idB = tid * 2, bj = idB >> 3, bk = idB & 7;

#pragma unroll 1
    for (int pass = 0; pass < 2; pass++) {
        const float* A = pass ? A1 : A0;
        const float* W = pass ? W1 : W0;
        if (A == nullptr) continue;
        for (int k0 = 0; k0 < K; k0 += 8) {
            {
                const float* ap = A + (size_t)(bm + am) * K + k0 + ak;
                bool rok = (bm + am) < M;
#pragma unroll
                for (int i = 0; i < 4; i++) {
                    float v = 0.0f;
                    if (rok && (k0 + ak + i) < K) v = ap[i];
                    As[ak + i][am] = v;
                }
            }
            {
#pragma unroll
                for (int i = 0; i < 2; i++) {
                    float v = 0.0f;
                    int col = bn + bj, kk = k0 + bk + i;
                    if (col < NC && kk < K) v = W[(size_t)col * K + kk];
                    Bs[bk + i][bj] = v;
                }
            }
            __syncthreads();
#pragma unroll
            for (int k = 0; k < 8; k++) {
                float a[8], b[4];
#pragma unroll
                for (int i = 0; i < 8; i++) a[i] = As[k][ty * 8 + i];
#pragma unroll
                for (int j = 0; j < 4; j++) b[j] = Bs[k][tx * 4 + j];
#pragma unroll
                for (int i = 0; i < 8; i++)
#pragma unroll
                    for (int j = 0; j < 4; j++) acc[i][j] = fmaf(a[i], b[j], acc[i][j]);
            }
            __syncthreads();
        }
    }
#pragma unroll
    for (int i = 0; i < 8; i++) {
        int r = bm + ty * 8 + i;
        if (r >= M) continue;
#pragma unroll
        for (int j = 0; j < 4; j++) {
            int c = bn + tx * 4 + j;
            if (c >= NC) continue;
            out[(size_t)r * NC + c] = acc[i][j] + bias[c];
        }
    }
}

// ================= HMMA GEMM, pre-split bf16, cp.async, 2 CTAs/SM =================
// mode 0: out = f32 (bias only); mode 1: BN+ReLU -> bf16 pair; mode 2: BN+ReLU -> f32
#define MM_STRIDE 80
#define MM_TILE   (128 * MM_STRIDE)
#define OFF_AH    0
#define OFF_AL    (1 * MM_TILE)
#define OFF_BH    (2 * MM_TILE)
#define OFF_BL    (3 * MM_TILE)
#define STAGE_B   (4 * MM_TILE)
#define SMEM_MMA  (2 * STAGE_B)

__global__ __launch_bounds__(256, 2)
void k_mma(const u16* __restrict__ A0h, const u16* __restrict__ A0l,
           const u16* __restrict__ W0h, const u16* __restrict__ W0l,
           const u16* __restrict__ A1h, const u16* __restrict__ A1l,
           const u16* __restrict__ W1h, const u16* __restrict__ W1l,
           const float* __restrict__ bias, float* __restrict__ outF,
           u16* __restrict__ outHi, u16* __restrict__ outLo, int mode,
           const float* __restrict__ bng, const float* __restrict__ bnb,
           const float* __restrict__ bnm, const float* __restrict__ bnv) {
    extern __shared__ char sm[];
    const int M = N_NODES;
    int tid = threadIdx.x, lane = tid & 31, wid = tid >> 5;
    int bm = blockIdx.y * 128, bn = blockIdx.x * 128;
    int warp_m = wid & 3, warp_n = wid >> 2;

    float acc[2][8][4];
#pragma unroll
    for (int mb = 0; mb < 2; mb++)
#pragma unroll
        for (int nb = 0; nb < 8; nb++)
#pragma unroll
            for (int q = 0; q < 4; q++) acc[mb][nb][q] = 0.0f;

    int lrow = tid >> 1, half = tid & 1;
    bool aok = (bm + lrow) < M;
    int abytes = aok ? 16 : 0;
    const int nsrc = (A1h != nullptr) ? 2 : 1;
    const int nch = nsrc * 12;

    uint32_t smb = smem_u32(sm);
    uint32_t ldst = smb + (uint32_t)lrow * MM_STRIDE + half * 32;

    // async-load one 32-k chunk (4 tiles) into a stage
    auto load_stage = [&](int ch, int stage) {
        int s = (ch < 12) ? 0 : 1;
        const u16* Ah = s ? A1h : A0h;
        const u16* Al = s ? A1l : A0l;
        const u16* Bh = s ? W1h : W0h;
        const u16* Bl = s ? W1l : W0l;
        int k0 = (ch - s * 12) * 32;
        size_t ao = aok ? ((size_t)(bm + lrow) * HID + k0 + half * 16) : 0;
        size_t bo = (size_t)(bn + lrow) * HID + k0 + half * 16;
        uint32_t d = ldst + stage * STAGE_B;
        cpasync16(d + OFF_AH,      Ah + ao,     abytes);
        cpasync16(d + OFF_AH + 16, Ah + ao + 8, abytes);
        cpasync16(d + OFF_AL,      Al + ao,     abytes);
        cpasync16(d + OFF_AL + 16, Al + ao + 8, abytes);
        cpasync16(d + OFF_BH,      Bh + bo,     16);
        cpasync16(d + OFF_BH + 16, Bh + bo + 8, 16);
        cpasync16(d + OFF_BL,      Bl + bo,     16);
        cpasync16(d + OFF_BL + 16, Bl + bo + 8, 16);
        asm volatile("cp.async.commit_group;" ::: "memory");
    };

    int l15 = lane & 15, kh = lane >> 4;
    uint32_t aoff = (uint32_t)(warp_m * 32 + l15) * MM_STRIDE + kh * 16;
    uint32_t boff = (uint32_t)(warp_n * 64 + l15) * MM_STRIDE + kh * 16;

    auto mmastage = [&](int stage) {
        uint32_t sb = smb + stage * STAGE_B;
#pragma unroll
        for (int s = 0; s < 2; s++) {
            uint32_t ko = s * 32;
            uint32_t ahf[2][4], alf[2][4], bhf[4][4], blf[4][4];
#pragma unroll
            for (int mb = 0; mb < 2; mb++) {
                LDM4(ahf[mb], sb + OFF_AH + aoff + mb * (16 * MM_STRIDE) + ko);
                LDM4(alf[mb], sb + OFF_AL + aoff + mb * (16 * MM_STRIDE) + ko);
            }
#pragma unroll
            for (int pb = 0; pb < 4; pb++) {
                LDM4(bhf[pb], sb + OFF_BH + boff + pb * (16 * MM_STRIDE) + ko);
                LDM4(blf[pb], sb + OFF_BL + boff + pb * (16 * MM_STRIDE) + ko);
            }
#pragma unroll
            for (int mb = 0; mb < 2; mb++)
#pragma unroll
                for (int nb = 0; nb < 8; nb++) {
                    int pb = nb >> 1, sel = nb & 1;
                    MMA16816(acc[mb][nb], ahf[mb], bhf[pb][sel], bhf[pb][sel + 2]);
                    MMA16816(acc[mb][nb], ahf[mb], blf[pb][sel], blf[pb][sel + 2]);
                    MMA16816(acc[mb][nb], alf[mb], bhf[pb][sel], bhf[pb][sel + 2]);
                }
        }
    };

    load_stage(0, 0);
#pragma unroll 1
    for (int ch = 0; ch < nch; ch++) {
        __syncthreads();   // all warps done reading the stage about to be overwritten
        if (ch + 1 < nch) {
            load_stage(ch + 1, (ch + 1) & 1);
            asm volatile("cp.async.wait_group 1;" ::: "memory");
        } else {
            asm volatile("cp.async.wait_group 0;" ::: "memory");
        }
        __syncthreads();   // current stage visible to all warps
        mmastage(ch & 1);
    }

    // epilogue
    int g = lane >> 2, tg = lane & 3;
#pragma unroll
    for (int mb = 0; mb < 2; mb++) {
#pragma unroll
        for (int hr = 0; hr < 2; hr++) {
            int r = bm + warp_m * 32 + mb * 16 + g + hr * 8;
            if (r >= M) continue;
#pragma unroll
            for (int nb = 0; nb < 8; nb++) {
                int c = bn + warp_n * 64 + nb * 8 + tg * 2;
                float v0 = acc[mb][nb][hr * 2 + 0] + __ldg(&bias[c]);
                float v1 = acc[mb][nb][hr * 2 + 1] + __ldg(&bias[c + 1]);
                if (mode != 0) {
                    v0 = (v0 - __ldg(&bnm[c])) * rsqrtf(__ldg(&bnv[c]) + BN_EPS) * __ldg(&bng[c]) + __ldg(&bnb[c]);
                    v1 = (v1 - __ldg(&bnm[c + 1])) * rsqrtf(__ldg(&bnv[c + 1]) + BN_EPS) * __ldg(&bng[c + 1]) + __ldg(&bnb[c + 1]);
                    v0 = fmaxf(v0, 0.0f);
                    v1 = fmaxf(v1, 0.0f);
                }
                size_t off = (size_t)r * HID + c;
                if (mode == 1) {
                    ushort2 hp, lp;
                    split_bf16(v0, hp.x, lp.x);
                    split_bf16(v1, hp.y, lp.y);
                    *(ushort2*)(outHi + off) = hp;
                    *(ushort2*)(outLo + off) = lp;
                } else {
                    *(float2*)(outF + off) = make_float2(v0, v1);
                }
            }
        }
    }
}

// ================= fused L2 norm + BN + ELU (bf16 pair out only) =================
__global__ void k_norm_bn_elu(const float* __restrict__ in,
                              u16* __restrict__ hhi, u16* __restrict__ hlo,
                              const float* __restrict__ g, const float* __restrict__ b,
                              const float* __restrict__ m, const float* __restrict__ v) {
    int w = (blockIdx.x * blockDim.x + threadIdx.x) >> 5;
    int lane = threadIdx.x & 31;
    if (w >= N_NODES) return;
    const float* row = in + (size_t)w * HID;
    float vals[12];
    float ss = 0.0f;
#pragma unroll
    for (int i = 0; i < 12; i++) {
        float x = row[lane + 32 * i];
        vals[i] = x;
        ss += x * x;
    }
#pragma unroll
    for (int o = 16; o > 0; o >>= 1) ss += __shfl_xor_sync(0xffffffff, ss, o);
    float inv = 1.0f / fmaxf(sqrtf(ss), 1e-12f);
#pragma unroll
    for (int i = 0; i < 12; i++) {
        int c = lane + 32 * i;
        float x = vals[i] * inv;
        x = (x - m[c]) * rsqrtf(v[c] + BN_EPS) * g[c] + b[c];
        x = x > 0.0f ? x : expm1f(x);
        u16 hh, ll;
        split_bf16(x, hh, ll);
        hhi[(size_t)w * HID + c] = hh;
        hlo[(size_t)w * HID + c] = ll;
    }
}

// ================= final projection 384 -> 3 =================
__global__ void k_final(const float* __restrict__ h, const float* __restrict__ W,
                        const float* __restrict__ bias, float* __restrict__ out) {
    int w = (blockIdx.x * blockDim.x + threadIdx.x) >> 5;
    int lane = threadIdx.x & 31;
    if (w >= N_NODES) return;
    const float* row = h + (size_t)w * HID;
    float vals[12];
#pragma unroll
    for (int i = 0; i < 12; i++) vals[i] = row[lane + 32 * i];
#pragma unroll
    for (int o = 0; o < OUT_DIM; o++) {
        float s = 0.0f;
        const float* wr = W + (size_t)o * HID;
#pragma unroll
        for (int i = 0; i < 12; i++) s += vals[i] * __ldg(&wr[lane + 32 * i]);
#pragma unroll
        for (int off = 16; off > 0; off >>= 1) s += __shfl_xor_sync(0xffffffff, s, off);
        if (lane == 0) out[(size_t)w * OUT_DIM + o] = s + bias[o];
    }
}

// ================= driver =================
extern "C" void kernel_launch(void* const* d_in, const int* in_sizes, int n_in,
                              void* d_out, int out_size) {
    const float* x    = (const float*)d_in[0];
    const int*   ei   = (const int*)d_in[1];
    const float* W_l0 = (const float*)d_in[2];
    const float* b_l0 = (const float*)d_in[3];
    const float* W_r0 = (const float*)d_in[4];
    const float* W_l  = (const float*)d_in[5];
    const float* b_l  = (const float*)d_in[6];
    const float* W_r  = (const float*)d_in[7];
    const float* bn_g = (const float*)d_in[8];
    const float* bn_b = (const float*)d_in[9];
    const float* bn_m = (const float*)d_in[10];
    const float* bn_v = (const float*)d_in[11];
    const float* Wp0  = (const float*)d_in[12];
    const float* bp0  = (const float*)d_in[13];
    const float* Wp1  = (const float*)d_in[14];
    const float* bp1  = (const float*)d_in[15];
    const float* Wp2  = (const float*)d_in[16];
    const float* bp2  = (const float*)d_in[17];
    const float* pbn_g = (const float*)d_in[18];
    const float* pbn_b = (const float*)d_in[19];
    const float* pbn_m = (const float*)d_in[20];
    const float* pbn_v = (const float*)d_in[21];
    float* out = (float*)d_out;

    const int* src = ei;
    const int* dst = ei + EDGES;

    float *bufB, *bufC, *agg10;
    int* cnt;
    u16 *whi, *wlo, *hhi, *hlo, *agh, *agl;
    cudaGetSymbolAddress((void**)&bufB, g_bufB);
    cudaGetSymbolAddress((void**)&bufC, g_bufC);
    cudaGetSymbolAddress((void**)&agg10, g_agg10);
    cudaGetSymbolAddress((void**)&cnt, g_cnt);
    cudaGetSymbolAddress((void**)&whi, g_whi);
    cudaGetSymbolAddress((void**)&wlo, g_wlo);
    cudaGetSymbolAddress((void**)&hhi, g_hhi);
    cudaGetSymbolAddress((void**)&hlo, g_hlo);
    cudaGetSymbolAddress((void**)&agh, g_agh);
    cudaGetSymbolAddress((void**)&agl, g_agl);

    cudaFuncSetAttribute(k_mma, cudaFuncAttributeMaxDynamicSharedMemorySize, SMEM_MMA);

    const int NB = (N_NODES + 511) / 512;
    const int WSZ = HID * HID;   // 147456

    // graph preprocessing
    cudaMemsetAsync(cnt, 0, N_NODES * sizeof(int), 0);
    k_count<<<(EDGES + 255) / 256, 256>>>(dst);
    k_inv<<<(N_NODES + 255) / 256, 256>>>();
    k_scan1<<<NB, 512>>>();
    k_scan2<<<1, 32>>>(NB);
    k_scan3<<<NB, 512>>>();
    k_fill<<<(EDGES + 255) / 256, 256>>>(src, dst);

    // weight pre-split: [Wl x4 | Wr x4 | Wp0 | Wp1]
    k_conv<<<(4 * WSZ + 255) / 256, 256>>>(W_l, whi, wlo, 4 * WSZ);
    k_conv<<<(4 * WSZ + 255) / 256, 256>>>(W_r, whi + 4 * WSZ, wlo + 4 * WSZ, 4 * WSZ);
    k_conv<<<(WSZ + 255) / 256, 256>>>(Wp0, whi + 8 * WSZ, wlo + 8 * WSZ, WSZ);
    k_conv<<<(WSZ + 255) / 256, 256>>>(Wp1, whi + 9 * WSZ, wlo + 9 * WSZ, WSZ);

    const int normBlocks = (N_NODES * 32 + 255) / 256;
    dim3 ggM(3, (N_NODES + 127) / 128);
    dim3 gg0(HID / 64, (N_NODES + 127) / 128);

    // ---- layer 0 (K=10, SIMT) ----
    k_gather10<<<(N_NODES + 255) / 256, 256>>>(x, agg10);
    k_gemm<<<gg0, 256>>>(agg10, W_l0, x, W_r0, b_l0, bufC, N_NODES, IN_DIM, HID);
    k_norm_bn_elu<<<normBlocks, 256>>>(bufC, hhi, hlo, bn_g, bn_b, bn_m, bn_v);

    // ---- layers 1..4 (HMMA, pre-split) ----
    for (int t = 1; t < 5; t++) {
        k_gather384<<<(N_NODES + 7) / 8, 256>>>(hhi, hlo, agh, agl);
        const u16* wlh = whi + (size_t)(t - 1) * WSZ;
        const u16* wll = wlo + (size_t)(t - 1) * WSZ;
        const u16* wrh = whi + (size_t)(4 + t - 1) * WSZ;
        const u16* wrl = wlo + (size_t)(4 + t - 1) * WSZ;
        const float* bl = b_l + (size_t)(t - 1) * HID;
        k_mma<<<ggM, 256, SMEM_MMA>>>(agh, agl, wlh, wll, hhi, hlo, wrh, wrl,
                                      bl, bufC, nullptr, nullptr, 0,
                                      nullptr, nullptr, nullptr, nullptr);
        k_norm_bn_elu<<<normBlocks, 256>>>(bufC, hhi, hlo,
                                           bn_g + t * HID, bn_b + t * HID,
                                           bn_m + t * HID, bn_v + t * HID);
    }

    // ---- projection MLP ----
    // proj0: in = h pair, out = bf16 pair (agh/agl reused)
    k_mma<<<ggM, 256, SMEM_MMA>>>(hhi, hlo, whi + 8 * WSZ, wlo + 8 * WSZ,
                                  nullptr, nullptr, nullptr, nullptr,
                                  bp0, nullptr, agh, agl, 1,
                                  pbn_g, pbn_b, pbn_m, pbn_v);
    // proj1: in = pair, out = f32 bufB
    k_mma<<<ggM, 256, SMEM_MMA>>>(agh, agl, whi + 9 * WSZ, wlo + 9 * WSZ,
                                  nullptr, nullptr, nullptr, nullptr,
                                  bp1, bufB, nullptr, nullptr, 2,
                                  pbn_g + HID, pbn_b + HID, pbn_m + HID, pbn_v + HID);
    k_final<<<normBlocks, 256>>>(bufB, Wp2, bp2, out);
}